// round 1
// baseline (speedup 1.0000x reference)
#include <cuda_runtime.h>

// Problem constants
constexpr int B_  = 4;
constexpr int T_  = 2048;
constexpr int D_  = 1024;
constexpr int H_  = 16;
constexpr int HD_ = 64;
constexpr int MROWS = B_ * T_;   // 8192

// Scratch (device globals: allocation-free)
__device__ float g_q[(size_t)B_ * H_ * T_ * HD_];
__device__ float g_k[(size_t)B_ * H_ * T_ * HD_];
__device__ float g_v[(size_t)B_ * H_ * T_ * HD_];
__device__ float g_o[(size_t)MROWS * D_];

// ---------------------------------------------------------------------------
// SGEMM mainloop: acc[8][8] += A_tile[128,K] @ W_tile[128,K]^T
// A is [M,K] row-major, W is [N,K] row-major (so Y = A @ W^T).
// BM=BN=128, BK=8, 256 threads, 8x8 per thread, register prefetch.
// ---------------------------------------------------------------------------
__device__ __forceinline__ void sgemm_main(const float* __restrict__ A,
                                           const float* __restrict__ W,
                                           float acc[8][8],
                                           int bm0, int bn0)
{
    constexpr int K = D_;
    __shared__ float As[8][128];
    __shared__ float Bs[8][128];

    const int tid = threadIdx.x;
    const int lr  = tid >> 1;          // 0..127
    const int lc  = (tid & 1) * 4;     // 0 or 4
    const int tm0 = (tid >> 4) * 8;
    const int tn0 = (tid & 15) * 8;

    const float* Aptr = A + (size_t)(bm0 + lr) * K + lc;
    const float* Wptr = W + (size_t)(bn0 + lr) * K + lc;

    float4 a = *(const float4*)(Aptr);
    float4 w = *(const float4*)(Wptr);

    for (int k0 = 0; k0 < K; k0 += 8) {
        As[lc + 0][lr] = a.x; As[lc + 1][lr] = a.y;
        As[lc + 2][lr] = a.z; As[lc + 3][lr] = a.w;
        Bs[lc + 0][lr] = w.x; Bs[lc + 1][lr] = w.y;
        Bs[lc + 2][lr] = w.z; Bs[lc + 3][lr] = w.w;
        __syncthreads();

        if (k0 + 8 < K) {
            a = *(const float4*)(Aptr + k0 + 8);
            w = *(const float4*)(Wptr + k0 + 8);
        }

        #pragma unroll
        for (int kk = 0; kk < 8; kk++) {
            float ra[8], rb[8];
            *(float4*)(ra)     = *(const float4*)&As[kk][tm0];
            *(float4*)(ra + 4) = *(const float4*)&As[kk][tm0 + 4];
            *(float4*)(rb)     = *(const float4*)&Bs[kk][tn0];
            *(float4*)(rb + 4) = *(const float4*)&Bs[kk][tn0 + 4];
            #pragma unroll
            for (int i = 0; i < 8; i++)
                #pragma unroll
                for (int j = 0; j < 8; j++)
                    acc[i][j] = fmaf(ra[i], rb[j], acc[i][j]);
        }
        __syncthreads();
    }
}

// QKV projection: Y = x @ W^T + b, scattered into [B, H, T, HD] layout.
// which: 0 -> g_q, 1 -> g_k, 2 -> g_v
__global__ void __launch_bounds__(256)
sgemm_qkv(const float* __restrict__ x,
          const float* __restrict__ W,
          const float* __restrict__ bias,
          int which)
{
    float* Y = (which == 0) ? g_q : (which == 1) ? g_k : g_v;

    const int bn0 = blockIdx.x * 128;
    const int bm0 = blockIdx.y * 128;
    const int tid = threadIdx.x;
    const int tm0 = (tid >> 4) * 8;
    const int tn0 = (tid & 15) * 8;

    float acc[8][8];
    #pragma unroll
    for (int i = 0; i < 8; i++)
        #pragma unroll
        for (int j = 0; j < 8; j++) acc[i][j] = 0.f;

    sgemm_main(x, W, acc, bm0, bn0);

    #pragma unroll
    for (int i = 0; i < 8; i++) {
        const int m  = bm0 + tm0 + i;
        const int bb = m >> 11;           // / T_
        const int t  = m & (T_ - 1);
        #pragma unroll
        for (int j = 0; j < 8; j++) {
            const int n  = bn0 + tn0 + j;
            const int h  = n >> 6;        // / HD_
            const int hd = n & (HD_ - 1);
            Y[(((size_t)bb * H_ + h) * T_ + t) * HD_ + hd] = acc[i][j] + bias[n];
        }
    }
}

// Output projection: out = g_o @ Wo^T + bo, plain row-major [MROWS, D_]
__global__ void __launch_bounds__(256)
sgemm_out(const float* __restrict__ Wo,
          const float* __restrict__ bo,
          float* __restrict__ Y)
{
    const int bn0 = blockIdx.x * 128;
    const int bm0 = blockIdx.y * 128;
    const int tid = threadIdx.x;
    const int tm0 = (tid >> 4) * 8;
    const int tn0 = (tid & 15) * 8;

    float acc[8][8];
    #pragma unroll
    for (int i = 0; i < 8; i++)
        #pragma unroll
        for (int j = 0; j < 8; j++) acc[i][j] = 0.f;

    sgemm_main(g_o, Wo, acc, bm0, bn0);

    #pragma unroll
    for (int i = 0; i < 8; i++) {
        const int m = bm0 + tm0 + i;
        #pragma unroll
        for (int j = 0; j < 8; j++) {
            const int n = bn0 + tn0 + j;
            Y[(size_t)m * D_ + n] = acc[i][j] + bo[n];
        }
    }
}

// ---------------------------------------------------------------------------
// Flash attention: per (b*h, q-tile of 64). Br=Bc=64, online softmax.
// 256 threads as 16x16, each owning a 4x4 fragment.
// Writes O into [B, T, H*HD] row-major layout (ready for final GEMM).
// ---------------------------------------------------------------------------
constexpr int LDSP = 65;                         // padded row
constexpr int ATTN_SMEM = 4 * 64 * LDSP * 4;     // Qs,Ks,Vs,Ps = 66560 B

__global__ void __launch_bounds__(256)
flash_attn()
{
    extern __shared__ float sm[];
    float (*Qs)[LDSP] = (float(*)[LDSP])(sm);
    float (*Ks)[LDSP] = (float(*)[LDSP])(sm + 64 * LDSP);
    float (*Vs)[LDSP] = (float(*)[LDSP])(sm + 2 * 64 * LDSP);
    float (*Ps)[LDSP] = (float(*)[LDSP])(sm + 3 * 64 * LDSP);

    const int bh = blockIdx.x;           // 0..63
    const int q0 = blockIdx.y * 64;
    const float* Qg = g_q + (size_t)bh * T_ * HD_;
    const float* Kg = g_k + (size_t)bh * T_ * HD_;
    const float* Vg = g_v + (size_t)bh * T_ * HD_;

    const int tid = threadIdx.x;
    const int tx  = tid & 15;
    const int ty  = tid >> 4;
    const float scale = 0.125f;          // 1/sqrt(64)

    // Load Q tile, pre-scaled
    for (int idx = tid; idx < 64 * 16; idx += 256) {
        const int r = idx >> 4;
        const int c = (idx & 15) * 4;
        float4 qv = *(const float4*)(Qg + (size_t)(q0 + r) * HD_ + c);
        Qs[r][c + 0] = qv.x * scale;
        Qs[r][c + 1] = qv.y * scale;
        Qs[r][c + 2] = qv.z * scale;
        Qs[r][c + 3] = qv.w * scale;
    }

    float m_i[4], l_i[4], o[4][4];
    #pragma unroll
    for (int i = 0; i < 4; i++) {
        m_i[i] = -1e30f;
        l_i[i] = 0.f;
        #pragma unroll
        for (int j = 0; j < 4; j++) o[i][j] = 0.f;
    }

    for (int j0 = 0; j0 < T_; j0 += 64) {
        __syncthreads();   // previous iteration's reads of Ks/Vs/Ps done
        for (int idx = tid; idx < 64 * 16; idx += 256) {
            const int r = idx >> 4;
            const int c = (idx & 15) * 4;
            float4 kv = *(const float4*)(Kg + (size_t)(j0 + r) * HD_ + c);
            Ks[r][c + 0] = kv.x; Ks[r][c + 1] = kv.y;
            Ks[r][c + 2] = kv.z; Ks[r][c + 3] = kv.w;
            float4 vv = *(const float4*)(Vg + (size_t)(j0 + r) * HD_ + c);
            Vs[r][c + 0] = vv.x; Vs[r][c + 1] = vv.y;
            Vs[r][c + 2] = vv.z; Vs[r][c + 3] = vv.w;
        }
        __syncthreads();

        // S = Q_tile @ K_tile^T (already scaled via Q)
        float s[4][4];
        #pragma unroll
        for (int i = 0; i < 4; i++)
            #pragma unroll
            for (int j = 0; j < 4; j++) s[i][j] = 0.f;

        #pragma unroll 4
        for (int hd = 0; hd < HD_; hd++) {
            float qv[4], kv[4];
            #pragma unroll
            for (int i = 0; i < 4; i++) qv[i] = Qs[4 * ty + i][hd];
            #pragma unroll
            for (int j = 0; j < 4; j++) kv[j] = Ks[4 * tx + j][hd];
            #pragma unroll
            for (int i = 0; i < 4; i++)
                #pragma unroll
                for (int j = 0; j < 4; j++)
                    s[i][j] = fmaf(qv[i], kv[j], s[i][j]);
        }

        // Online softmax per row; stage P into smem
        #pragma unroll
        for (int i = 0; i < 4; i++) {
            float mx = s[i][0];
            #pragma unroll
            for (int j = 1; j < 4; j++) mx = fmaxf(mx, s[i][j]);
            #pragma unroll
            for (int off = 8; off >= 1; off >>= 1)
                mx = fmaxf(mx, __shfl_xor_sync(0xffffffffu, mx, off, 16));

            const float m_new = fmaxf(m_i[i], mx);
            const float alpha = __expf(m_i[i] - m_new);

            float rs = 0.f;
            #pragma unroll
            for (int j = 0; j < 4; j++) {
                s[i][j] = __expf(s[i][j] - m_new);
                rs += s[i][j];
            }
            #pragma unroll
            for (int off = 8; off >= 1; off >>= 1)
                rs += __shfl_xor_sync(0xffffffffu, rs, off, 16);

            l_i[i] = l_i[i] * alpha + rs;
            m_i[i] = m_new;
            #pragma unroll
            for (int j = 0; j < 4; j++) {
                o[i][j] *= alpha;
                Ps[4 * ty + i][4 * tx + j] = s[i][j];
            }
        }
        __syncthreads();

        // O += P @ V_tile
        #pragma unroll 4
        for (int kk = 0; kk < 64; kk++) {
            float pv[4], vv[4];
            #pragma unroll
            for (int i = 0; i < 4; i++) pv[i] = Ps[4 * ty + i][kk];
            #pragma unroll
            for (int j = 0; j < 4; j++) vv[j] = Vs[kk][4 * tx + j];
            #pragma unroll
            for (int i = 0; i < 4; i++)
                #pragma unroll
                for (int j = 0; j < 4; j++)
                    o[i][j] = fmaf(pv[i], vv[j], o[i][j]);
        }
    }

    // Epilogue: normalize + write into [B, T, H*HD] layout
    const int bb = bh >> 4;   // / H_
    const int h  = bh & 15;
    #pragma unroll
    for (int i = 0; i < 4; i++) {
        const float inv = 1.0f / l_i[i];
        const int row = q0 + 4 * ty + i;
        #pragma unroll
        for (int j = 0; j < 4; j++) {
            g_o[((size_t)bb * T_ + row) * D_ + h * HD_ + 4 * tx + j] = o[i][j] * inv;
        }
    }
}

// ---------------------------------------------------------------------------
extern "C" void kernel_launch(void* const* d_in, const int* in_sizes, int n_in,
                              void* d_out, int out_size)
{
    const float* x  = (const float*)d_in[0];
    const float* Wq = (const float*)d_in[1];
    const float* bq = (const float*)d_in[2];
    const float* Wk = (const float*)d_in[3];
    const float* bk = (const float*)d_in[4];
    const float* Wv = (const float*)d_in[5];
    const float* bv = (const float*)d_in[6];
    const float* Wo = (const float*)d_in[7];
    const float* bo = (const float*)d_in[8];
    float* out = (float*)d_out;

    static bool attr_set = false;
    // cudaFuncSetAttribute is idempotent & not a stream op; safe under capture.
    cudaFuncSetAttribute(flash_attn,
                         cudaFuncAttributeMaxDynamicSharedMemorySize,
                         ATTN_SMEM);
    (void)attr_set;

    dim3 gemm_grid(D_ / 128, MROWS / 128);   // (8, 64)
    sgemm_qkv<<<gemm_grid, 256>>>(x, Wq, bq, 0);
    sgemm_qkv<<<gemm_grid, 256>>>(x, Wk, bk, 1);
    sgemm_qkv<<<gemm_grid, 256>>>(x, Wv, bv, 2);

    dim3 attn_grid(B_ * H_, T_ / 64);        // (64, 32)
    flash_attn<<<attn_grid, 256, ATTN_SMEM>>>();

    sgemm_out<<<gemm_grid, 256>>>(Wo, bo, out);
}

// round 5
// speedup vs baseline: 1.4629x; 1.4629x over previous
#include <cuda_runtime.h>
#include <cstdint>

// Problem constants
constexpr int B_  = 4;
constexpr int T_  = 2048;
constexpr int D_  = 1024;
constexpr int H_  = 16;
constexpr int HD_ = 64;
constexpr int MROWS = B_ * T_;   // 8192
constexpr int KDIM  = D_;        // 1024

// Scratch (device globals: allocation-free)
__device__ float g_q[(size_t)B_ * H_ * T_ * HD_];
__device__ float g_k[(size_t)B_ * H_ * T_ * HD_];
__device__ float g_v[(size_t)B_ * H_ * T_ * HD_];
__device__ float g_o[(size_t)MROWS * D_];

// ---------------------------------------------------------------------------
// tf32 helpers (mma.sync path — works on plain sm_103 PTX target)
// ---------------------------------------------------------------------------
__device__ __forceinline__ uint32_t f2tf32(float f) {
    uint32_t u;
    asm("cvt.rna.tf32.f32 %0, %1;" : "=r"(u) : "f"(f));
    return u;
}

__device__ __forceinline__ void mma_tf32(float c[4], const uint32_t a[4],
                                         const uint32_t b[2]) {
    asm volatile(
        "mma.sync.aligned.m16n8k8.row.col.f32.tf32.tf32.f32 "
        "{%0,%1,%2,%3}, {%4,%5,%6,%7}, {%8,%9}, {%0,%1,%2,%3};"
        : "+f"(c[0]), "+f"(c[1]), "+f"(c[2]), "+f"(c[3])
        : "r"(a[0]), "r"(a[1]), "r"(a[2]), "r"(a[3]), "r"(b[0]), "r"(b[1]));
}

// ===========================================================================
// tf32 tensor-core GEMM:  Y[M,N] = A[M,K] @ W[N,K]^T + bias
// BM=BN=128, BK=32. 256 threads = 8 warps in 2(m) x 4(n); each warp owns a
// 64x32 tile = 4 m16-tiles x 4 n8-tiles of m16n8k8 mma.
// Smem stride 36 floats -> conflict-free fragment LDS (banks (4g+tg)%32).
// mode: 0/1/2 -> scatter into g_q/g_k/g_v as [B,H,T,HD]; 3 -> row-major Yext.
// ===========================================================================
constexpr int BKF = 32;
constexpr int LDS_S = 36;

__global__ void __launch_bounds__(256)
gemm_tc(const float* __restrict__ Aext,
        const float* __restrict__ W,
        const float* __restrict__ bias,
        float* __restrict__ Yext,
        int mode)
{
    __shared__ uint32_t As[128 * LDS_S];
    __shared__ uint32_t Bs[128 * LDS_S];

    const float* A = (mode == 3) ? g_o : Aext;
    float* Y = (mode == 0) ? g_q : (mode == 1) ? g_k : (mode == 2) ? g_v : Yext;

    const int bn0 = blockIdx.x * 128;
    const int bm0 = blockIdx.y * 128;

    const int tid  = threadIdx.x;
    const int lane = tid & 31;
    const int wid  = tid >> 5;
    const int g    = lane >> 2;      // group id 0..7
    const int tg   = lane & 3;       // thread-in-group 0..3
    const int wm   = (wid >> 2) * 64;  // warp m offset (0 or 64)
    const int wn   = (wid & 3) * 32;   // warp n offset (0..96)

    float acc[4][4][4];
    #pragma unroll
    for (int i = 0; i < 4; i++)
        #pragma unroll
        for (int j = 0; j < 4; j++)
            #pragma unroll
            for (int r = 0; r < 4; r++) acc[i][j][r] = 0.f;

    // Global load mapping: tile 128 rows x 32 floats = 1024 float4;
    // 4 float4 per thread; 8 float4 per row.
    const int lr4 = tid >> 3;        // base row (advances +32 per i)
    const int lc4 = tid & 7;         // float4 column within row

    const float4* gA = (const float4*)(A + (size_t)(bm0 + lr4) * KDIM) + lc4;
    const float4* gB = (const float4*)(W + (size_t)(bn0 + lr4) * KDIM) + lc4;
    const int rowStep4 = 32 * (KDIM / 4);   // 32 rows in float4 units

    float4 ra[4], rb[4];
    #pragma unroll
    for (int i = 0; i < 4; i++) {
        ra[i] = gA[(size_t)i * rowStep4];
        rb[i] = gB[(size_t)i * rowStep4];
    }

    const int NK = KDIM / BKF;   // 32 chunks
    for (int kc = 0; kc < NK; kc++) {
        if (kc > 0) __syncthreads();
        #pragma unroll
        for (int i = 0; i < 4; i++) {
            const int s = (lr4 + i * 32) * LDS_S + lc4 * 4;
            As[s + 0] = f2tf32(ra[i].x); As[s + 1] = f2tf32(ra[i].y);
            As[s + 2] = f2tf32(ra[i].z); As[s + 3] = f2tf32(ra[i].w);
            Bs[s + 0] = f2tf32(rb[i].x); Bs[s + 1] = f2tf32(rb[i].y);
            Bs[s + 2] = f2tf32(rb[i].z); Bs[s + 3] = f2tf32(rb[i].w);
        }
        __syncthreads();

        if (kc + 1 < NK) {
            const int koff = (kc + 1) * (BKF / 4);
            #pragma unroll
            for (int i = 0; i < 4; i++) {
                ra[i] = gA[(size_t)i * rowStep4 + koff];
                rb[i] = gB[(size_t)i * rowStep4 + koff];
            }
        }

        #pragma unroll
        for (int s = 0; s < 4; s++) {       // 4 x k8 steps per chunk
            uint32_t af[4][4];
            #pragma unroll
            for (int i = 0; i < 4; i++) {
                const int base = (wm + i * 16 + g) * LDS_S + s * 8 + tg;
                af[i][0] = As[base];
                af[i][1] = As[base + 8 * LDS_S];
                af[i][2] = As[base + 4];
                af[i][3] = As[base + 8 * LDS_S + 4];
            }
            uint32_t bf[4][2];
            #pragma unroll
            for (int j = 0; j < 4; j++) {
                const int base = (wn + j * 8 + g) * LDS_S + s * 8 + tg;
                bf[j][0] = Bs[base];
                bf[j][1] = Bs[base + 4];
            }
            #pragma unroll
            for (int i = 0; i < 4; i++)
                #pragma unroll
                for (int j = 0; j < 4; j++)
                    mma_tf32(acc[i][j], af[i], bf[j]);
        }
    }

    // Epilogue: bias + scatter.
    // c fragment: rows (g, g+8), cols (2tg, 2tg+1) within each m16n8 tile.
    #pragma unroll
    for (int j = 0; j < 4; j++) {
        const int n = bn0 + wn + j * 8 + 2 * tg;
        const float bx = bias[n], by = bias[n + 1];
        #pragma unroll
        for (int i = 0; i < 4; i++) {
            const int m0 = bm0 + wm + i * 16 + g;
            float2 v0 = make_float2(acc[i][j][0] + bx, acc[i][j][1] + by);
            float2 v1 = make_float2(acc[i][j][2] + bx, acc[i][j][3] + by);
            if (mode < 3) {
                const int h = n >> 6, hd = n & (HD_ - 1);
                const int bb0 = m0 >> 11, t0 = m0 & (T_ - 1);
                const int m1 = m0 + 8;
                const int bb1 = m1 >> 11, t1 = m1 & (T_ - 1);
                *(float2*)&Y[(((size_t)bb0 * H_ + h) * T_ + t0) * HD_ + hd] = v0;
                *(float2*)&Y[(((size_t)bb1 * H_ + h) * T_ + t1) * HD_ + hd] = v1;
            } else {
                *(float2*)&Y[(size_t)m0 * D_ + n] = v0;
                *(float2*)&Y[(size_t)(m0 + 8) * D_ + n] = v1;
            }
        }
    }
}

// ---------------------------------------------------------------------------
// Flash attention (unchanged, known-correct): per (b*h, q-tile of 64).
// ---------------------------------------------------------------------------
constexpr int LDSP = 65;
constexpr int ATTN_SMEM = 4 * 64 * LDSP * 4;

__global__ void __launch_bounds__(256)
flash_attn()
{
    extern __shared__ float smf[];
    float (*Qs)[LDSP] = (float(*)[LDSP])(smf);
    float (*Ks)[LDSP] = (float(*)[LDSP])(smf + 64 * LDSP);
    float (*Vs)[LDSP] = (float(*)[LDSP])(smf + 2 * 64 * LDSP);
    float (*Ps)[LDSP] = (float(*)[LDSP])(smf + 3 * 64 * LDSP);

    const int bh = blockIdx.x;
    const int q0 = blockIdx.y * 64;
    const float* Qg = g_q + (size_t)bh * T_ * HD_;
    const float* Kg = g_k + (size_t)bh * T_ * HD_;
    const float* Vg = g_v + (size_t)bh * T_ * HD_;

    const int tid = threadIdx.x;
    const int tx  = tid & 15;
    const int ty  = tid >> 4;
    const float scale = 0.125f;

    for (int idx = tid; idx < 64 * 16; idx += 256) {
        const int r = idx >> 4;
        const int c = (idx & 15) * 4;
        float4 qv = *(const float4*)(Qg + (size_t)(q0 + r) * HD_ + c);
        Qs[r][c + 0] = qv.x * scale;
        Qs[r][c + 1] = qv.y * scale;
        Qs[r][c + 2] = qv.z * scale;
        Qs[r][c + 3] = qv.w * scale;
    }

    float m_i[4], l_i[4], o[4][4];
    #pragma unroll
    for (int i = 0; i < 4; i++) {
        m_i[i] = -1e30f;
        l_i[i] = 0.f;
        #pragma unroll
        for (int j = 0; j < 4; j++) o[i][j] = 0.f;
    }

    for (int j0 = 0; j0 < T_; j0 += 64) {
        __syncthreads();
        for (int idx = tid; idx < 64 * 16; idx += 256) {
            const int r = idx >> 4;
            const int c = (idx & 15) * 4;
            float4 kv = *(const float4*)(Kg + (size_t)(j0 + r) * HD_ + c);
            Ks[r][c + 0] = kv.x; Ks[r][c + 1] = kv.y;
            Ks[r][c + 2] = kv.z; Ks[r][c + 3] = kv.w;
            float4 vv = *(const float4*)(Vg + (size_t)(j0 + r) * HD_ + c);
            Vs[r][c + 0] = vv.x; Vs[r][c + 1] = vv.y;
            Vs[r][c + 2] = vv.z; Vs[r][c + 3] = vv.w;
        }
        __syncthreads();

        float s[4][4];
        #pragma unroll
        for (int i = 0; i < 4; i++)
            #pragma unroll
            for (int j = 0; j < 4; j++) s[i][j] = 0.f;

        #pragma unroll 4
        for (int hd = 0; hd < HD_; hd++) {
            float qv[4], kv[4];
            #pragma unroll
            for (int i = 0; i < 4; i++) qv[i] = Qs[4 * ty + i][hd];
            #pragma unroll
            for (int j = 0; j < 4; j++) kv[j] = Ks[4 * tx + j][hd];
            #pragma unroll
            for (int i = 0; i < 4; i++)
                #pragma unroll
                for (int j = 0; j < 4; j++)
                    s[i][j] = fmaf(qv[i], kv[j], s[i][j]);
        }

        #pragma unroll
        for (int i = 0; i < 4; i++) {
            float mx = s[i][0];
            #pragma unroll
            for (int j = 1; j < 4; j++) mx = fmaxf(mx, s[i][j]);
            #pragma unroll
            for (int off = 8; off >= 1; off >>= 1)
                mx = fmaxf(mx, __shfl_xor_sync(0xffffffffu, mx, off, 16));

            const float m_new = fmaxf(m_i[i], mx);
            const float alpha = __expf(m_i[i] - m_new);

            float rs = 0.f;
            #pragma unroll
            for (int j = 0; j < 4; j++) {
                s[i][j] = __expf(s[i][j] - m_new);
                rs += s[i][j];
            }
            #pragma unroll
            for (int off = 8; off >= 1; off >>= 1)
                rs += __shfl_xor_sync(0xffffffffu, rs, off, 16);

            l_i[i] = l_i[i] * alpha + rs;
            m_i[i] = m_new;
            #pragma unroll
            for (int j = 0; j < 4; j++) {
                o[i][j] *= alpha;
                Ps[4 * ty + i][4 * tx + j] = s[i][j];
            }
        }
        __syncthreads();

        #pragma unroll 4
        for (int kk = 0; kk < 64; kk++) {
            float pv[4], vv[4];
            #pragma unroll
            for (int i = 0; i < 4; i++) pv[i] = Ps[4 * ty + i][kk];
            #pragma unroll
            for (int j = 0; j < 4; j++) vv[j] = Vs[kk][4 * tx + j];
            #pragma unroll
            for (int i = 0; i < 4; i++)
                #pragma unroll
                for (int j = 0; j < 4; j++)
                    o[i][j] = fmaf(pv[i], vv[j], o[i][j]);
        }
    }

    const int bb = bh >> 4;
    const int h  = bh & 15;
    #pragma unroll
    for (int i = 0; i < 4; i++) {
        const float inv = 1.0f / l_i[i];
        const int row = q0 + 4 * ty + i;
        #pragma unroll
        for (int j = 0; j < 4; j++) {
            g_o[((size_t)bb * T_ + row) * D_ + h * HD_ + 4 * tx + j] = o[i][j] * inv;
        }
    }
}

// ---------------------------------------------------------------------------
extern "C" void kernel_launch(void* const* d_in, const int* in_sizes, int n_in,
                              void* d_out, int out_size)
{
    const float* x  = (const float*)d_in[0];
    const float* Wq = (const float*)d_in[1];
    const float* bq = (const float*)d_in[2];
    const float* Wk = (const float*)d_in[3];
    const float* bk = (const float*)d_in[4];
    const float* Wv = (const float*)d_in[5];
    const float* bv = (const float*)d_in[6];
    const float* Wo = (const float*)d_in[7];
    const float* bo = (const float*)d_in[8];
    float* out = (float*)d_out;

    cudaFuncSetAttribute(flash_attn, cudaFuncAttributeMaxDynamicSharedMemorySize,
                         ATTN_SMEM);

    dim3 gg(D_ / 128, MROWS / 128);          // (8, 64)
    gemm_tc<<<gg, 256>>>(x, Wq, bq, nullptr, 0);
    gemm_tc<<<gg, 256>>>(x, Wk, bk, nullptr, 1);
    gemm_tc<<<gg, 256>>>(x, Wv, bv, nullptr, 2);

    dim3 attn_grid(B_ * H_, T_ / 64);        // (64, 32)
    flash_attn<<<attn_grid, 256, ATTN_SMEM>>>();

    gemm_tc<<<gg, 256>>>(nullptr, Wo, bo, out, 3);
}

// round 6
// speedup vs baseline: 2.3285x; 1.5917x over previous
#include <cuda_runtime.h>
#include <cstdint>

// Problem constants
constexpr int B_  = 4;
constexpr int T_  = 2048;
constexpr int D_  = 1024;
constexpr int H_  = 16;
constexpr int HD_ = 64;
constexpr int MROWS = B_ * T_;   // 8192
constexpr int KDIM  = D_;        // 1024

// Scratch (device globals: allocation-free)
__device__ float g_q[(size_t)B_ * H_ * T_ * HD_];
__device__ float g_k[(size_t)B_ * H_ * T_ * HD_];
__device__ float g_v[(size_t)B_ * H_ * T_ * HD_];
__device__ float g_o[(size_t)MROWS * D_];

// ---------------------------------------------------------------------------
// tf32 helpers (mma.sync path — plain sm_103 PTX target)
// ---------------------------------------------------------------------------
__device__ __forceinline__ uint32_t f2tf32(float f) {
    uint32_t u;
    asm("cvt.rna.tf32.f32 %0, %1;" : "=r"(u) : "f"(f));
    return u;
}

__device__ __forceinline__ void mma_tf32(float c[4], const uint32_t a[4],
                                         const uint32_t b[2]) {
    asm volatile(
        "mma.sync.aligned.m16n8k8.row.col.f32.tf32.tf32.f32 "
        "{%0,%1,%2,%3}, {%4,%5,%6,%7}, {%8,%9}, {%0,%1,%2,%3};"
        : "+f"(c[0]), "+f"(c[1]), "+f"(c[2]), "+f"(c[3])
        : "r"(a[0]), "r"(a[1]), "r"(a[2]), "r"(a[3]), "r"(b[0]), "r"(b[1]));
}

// ===========================================================================
// tf32 tensor-core GEMM (unchanged from R3/R5)
// ===========================================================================
constexpr int BKF = 32;
constexpr int LDS_S = 36;

__global__ void __launch_bounds__(256)
gemm_tc(const float* __restrict__ Aext,
        const float* __restrict__ W,
        const float* __restrict__ bias,
        float* __restrict__ Yext,
        int mode)
{
    __shared__ uint32_t As[128 * LDS_S];
    __shared__ uint32_t Bs[128 * LDS_S];

    const float* A = (mode == 3) ? g_o : Aext;
    float* Y = (mode == 0) ? g_q : (mode == 1) ? g_k : (mode == 2) ? g_v : Yext;

    const int bn0 = blockIdx.x * 128;
    const int bm0 = blockIdx.y * 128;

    const int tid  = threadIdx.x;
    const int lane = tid & 31;
    const int wid  = tid >> 5;
    const int g    = lane >> 2;
    const int tg   = lane & 3;
    const int wm   = (wid >> 2) * 64;
    const int wn   = (wid & 3) * 32;

    float acc[4][4][4];
    #pragma unroll
    for (int i = 0; i < 4; i++)
        #pragma unroll
        for (int j = 0; j < 4; j++)
            #pragma unroll
            for (int r = 0; r < 4; r++) acc[i][j][r] = 0.f;

    const int lr4 = tid >> 3;
    const int lc4 = tid & 7;

    const float4* gA = (const float4*)(A + (size_t)(bm0 + lr4) * KDIM) + lc4;
    const float4* gB = (const float4*)(W + (size_t)(bn0 + lr4) * KDIM) + lc4;
    const int rowStep4 = 32 * (KDIM / 4);

    float4 ra[4], rb[4];
    #pragma unroll
    for (int i = 0; i < 4; i++) {
        ra[i] = gA[(size_t)i * rowStep4];
        rb[i] = gB[(size_t)i * rowStep4];
    }

    const int NK = KDIM / BKF;
    for (int kc = 0; kc < NK; kc++) {
        if (kc > 0) __syncthreads();
        #pragma unroll
        for (int i = 0; i < 4; i++) {
            const int s = (lr4 + i * 32) * LDS_S + lc4 * 4;
            As[s + 0] = f2tf32(ra[i].x); As[s + 1] = f2tf32(ra[i].y);
            As[s + 2] = f2tf32(ra[i].z); As[s + 3] = f2tf32(ra[i].w);
            Bs[s + 0] = f2tf32(rb[i].x); Bs[s + 1] = f2tf32(rb[i].y);
            Bs[s + 2] = f2tf32(rb[i].z); Bs[s + 3] = f2tf32(rb[i].w);
        }
        __syncthreads();

        if (kc + 1 < NK) {
            const int koff = (kc + 1) * (BKF / 4);
            #pragma unroll
            for (int i = 0; i < 4; i++) {
                ra[i] = gA[(size_t)i * rowStep4 + koff];
                rb[i] = gB[(size_t)i * rowStep4 + koff];
            }
        }

        #pragma unroll
        for (int s = 0; s < 4; s++) {
            uint32_t af[4][4];
            #pragma unroll
            for (int i = 0; i < 4; i++) {
                const int base = (wm + i * 16 + g) * LDS_S + s * 8 + tg;
                af[i][0] = As[base];
                af[i][1] = As[base + 8 * LDS_S];
                af[i][2] = As[base + 4];
                af[i][3] = As[base + 8 * LDS_S + 4];
            }
            uint32_t bf[4][2];
            #pragma unroll
            for (int j = 0; j < 4; j++) {
                const int base = (wn + j * 8 + g) * LDS_S + s * 8 + tg;
                bf[j][0] = Bs[base];
                bf[j][1] = Bs[base + 4];
            }
            #pragma unroll
            for (int i = 0; i < 4; i++)
                #pragma unroll
                for (int j = 0; j < 4; j++)
                    mma_tf32(acc[i][j], af[i], bf[j]);
        }
    }

    #pragma unroll
    for (int j = 0; j < 4; j++) {
        const int n = bn0 + wn + j * 8 + 2 * tg;
        const float bx = bias[n], by = bias[n + 1];
        #pragma unroll
        for (int i = 0; i < 4; i++) {
            const int m0 = bm0 + wm + i * 16 + g;
            float2 v0 = make_float2(acc[i][j][0] + bx, acc[i][j][1] + by);
            float2 v1 = make_float2(acc[i][j][2] + bx, acc[i][j][3] + by);
            if (mode < 3) {
                const int h = n >> 6, hd = n & (HD_ - 1);
                const int bb0 = m0 >> 11, t0 = m0 & (T_ - 1);
                const int m1 = m0 + 8;
                const int bb1 = m1 >> 11, t1 = m1 & (T_ - 1);
                *(float2*)&Y[(((size_t)bb0 * H_ + h) * T_ + t0) * HD_ + hd] = v0;
                *(float2*)&Y[(((size_t)bb1 * H_ + h) * T_ + t1) * HD_ + hd] = v1;
            } else {
                *(float2*)&Y[(size_t)m0 * D_ + n] = v0;
                *(float2*)&Y[(size_t)(m0 + 8) * D_ + n] = v1;
            }
        }
    }
}

// ===========================================================================
// Tensor-core flash attention (tf32 mma.sync).
// Per CTA: 128 queries (Br), Bc=64 key tile, 8 warps x 16 query rows.
// QK^T: 2-term tf32 split (near-fp32 logits). PV: single tf32.
// Pair-permuted smem column layout: within each k8 step, column c is stored
// at (c%4)*2 + (c/4), so each mma fragment pair (tg, tg+4) is one LDS.64.
// ===========================================================================
constexpr int FBr = 128, FBc = 64;
constexpr int FST = 68;                   // smem row stride (words)
constexpr int OFF_KHI = 0;
constexpr int OFF_KLO = 64 * FST;
constexpr int OFF_VT  = 2 * 64 * FST;
constexpr int OFF_PS  = 3 * 64 * FST;
constexpr int FLASH_SMEM = (3 * 64 + FBr) * FST * 4;   // 87040 B

__device__ __forceinline__ int permc(int c) {   // permute col within k8 step
    return ((c & 3) << 1) | (c >> 2);
}

__global__ void __launch_bounds__(256)
flash_tc()
{
    extern __shared__ uint32_t smw[];
    uint32_t* Khi = smw + OFF_KHI;
    uint32_t* Klo = smw + OFF_KLO;
    uint32_t* Vt  = smw + OFF_VT;
    uint32_t* Ps  = smw + OFF_PS;
    float*    Psf = (float*)Ps;

    const int bh = blockIdx.x;
    const int q0 = blockIdx.y * FBr;
    const float* Qg = g_q + (size_t)bh * T_ * HD_;
    const float* Kg = g_k + (size_t)bh * T_ * HD_;
    const float* Vg = g_v + (size_t)bh * T_ * HD_;

    const int tid = threadIdx.x, lane = tid & 31, wid = tid >> 5;
    const int g = lane >> 2, tg = lane & 3;
    const int wr = wid * 16;

    // ---- Stage Q (pre-scaled) into Ps, then extract hi/lo A-fragments ----
    #pragma unroll
    for (int i = 0; i < 8; i++) {               // 128 rows x 16 f4
        const int idx = tid + i * 256;
        const int r = idx >> 4, c4 = idx & 15;
        float4 q = *(const float4*)(Qg + (size_t)(q0 + r) * HD_ + c4 * 4);
        float* d = Psf + r * FST + c4 * 4;
        d[0] = q.x * 0.125f; d[1] = q.y * 0.125f;
        d[2] = q.z * 0.125f; d[3] = q.w * 0.125f;
    }
    __syncthreads();

    uint32_t qh[8][4], ql[8][4];
    #pragma unroll
    for (int s = 0; s < 8; s++) {
        float v[4];
        v[0] = Psf[(wr + g)     * FST + s * 8 + tg];
        v[1] = Psf[(wr + g + 8) * FST + s * 8 + tg];
        v[2] = Psf[(wr + g)     * FST + s * 8 + tg + 4];
        v[3] = Psf[(wr + g + 8) * FST + s * 8 + tg + 4];
        #pragma unroll
        for (int u = 0; u < 4; u++) {
            qh[s][u] = f2tf32(v[u]);
            ql[s][u] = f2tf32(v[u] - __uint_as_float(qh[s][u]));
        }
    }

    float o[8][4];
    #pragma unroll
    for (int j = 0; j < 8; j++)
        #pragma unroll
        for (int r = 0; r < 4; r++) o[j][r] = 0.f;
    float m0 = -1e30f, m1 = -1e30f, l0 = 0.f, l1 = 0.f;

    for (int j0 = 0; j0 < T_; j0 += FBc) {
        __syncthreads();   // previous iteration fully consumed K/Vt/Ps

        // ---- Load K (hi/lo split) and V (transposed), permuted columns ----
        #pragma unroll
        for (int i = 0; i < 4; i++) {           // 64 rows x 16 f4
            const int idx = tid + i * 256;
            const int r = idx >> 4, c4 = idx & 15;
            const int dbase = c4 * 4;
            float4 kv = *(const float4*)(Kg + (size_t)(j0 + r) * HD_ + c4 * 4);
            const float kf[4] = {kv.x, kv.y, kv.z, kv.w};
            #pragma unroll
            for (int u = 0; u < 4; u++) {
                const int d = dbase + u;
                const int pc = (d & ~7) + permc(d & 7);
                const uint32_t hi = f2tf32(kf[u]);
                Khi[r * FST + pc] = hi;
                Klo[r * FST + pc] = f2tf32(kf[u] - __uint_as_float(hi));
            }
            float4 vv = *(const float4*)(Vg + (size_t)(j0 + r) * HD_ + c4 * 4);
            const float vf[4] = {vv.x, vv.y, vv.z, vv.w};
            const int pj = (r & ~7) + permc(r & 7);
            #pragma unroll
            for (int u = 0; u < 4; u++)
                Vt[(dbase + u) * FST + pj] = f2tf32(vf[u]);
        }
        __syncthreads();

        // ---- S = Q @ K^T (split tf32) ----
        float sacc[8][4];
        #pragma unroll
        for (int j = 0; j < 8; j++)
            #pragma unroll
            for (int r = 0; r < 4; r++) sacc[j][r] = 0.f;

        #pragma unroll
        for (int s = 0; s < 8; s++) {
            #pragma unroll
            for (int jt = 0; jt < 8; jt++) {
                const uint2 kh2 = *(const uint2*)&Khi[(jt * 8 + g) * FST + s * 8 + 2 * tg];
                const uint2 kl2 = *(const uint2*)&Klo[(jt * 8 + g) * FST + s * 8 + 2 * tg];
                const uint32_t bhh[2] = {kh2.x, kh2.y};
                const uint32_t bll[2] = {kl2.x, kl2.y};
                mma_tf32(sacc[jt], qh[s], bhh);
                mma_tf32(sacc[jt], ql[s], bhh);
                mma_tf32(sacc[jt], qh[s], bll);
            }
        }

        // ---- Online softmax (rows g and g+8) ----
        float mx0 = -1e30f, mx1 = -1e30f;
        #pragma unroll
        for (int jt = 0; jt < 8; jt++) {
            mx0 = fmaxf(mx0, fmaxf(sacc[jt][0], sacc[jt][1]));
            mx1 = fmaxf(mx1, fmaxf(sacc[jt][2], sacc[jt][3]));
        }
        mx0 = fmaxf(mx0, __shfl_xor_sync(0xffffffffu, mx0, 1));
        mx0 = fmaxf(mx0, __shfl_xor_sync(0xffffffffu, mx0, 2));
        mx1 = fmaxf(mx1, __shfl_xor_sync(0xffffffffu, mx1, 1));
        mx1 = fmaxf(mx1, __shfl_xor_sync(0xffffffffu, mx1, 2));

        const float mn0 = fmaxf(m0, mx0), mn1 = fmaxf(m1, mx1);
        const float a0 = __expf(m0 - mn0), a1 = __expf(m1 - mn1);

        const int pc0 = permc(2 * tg);
        const int pc1 = permc(2 * tg + 1);
        float rs0 = 0.f, rs1 = 0.f;
        #pragma unroll
        for (int jt = 0; jt < 8; jt++) {
            const float e0 = __expf(sacc[jt][0] - mn0);
            const float e1 = __expf(sacc[jt][1] - mn0);
            const float e2 = __expf(sacc[jt][2] - mn1);
            const float e3 = __expf(sacc[jt][3] - mn1);
            rs0 += e0 + e1;
            rs1 += e2 + e3;
            Ps[(wr + g)     * FST + jt * 8 + pc0] = f2tf32(e0);
            Ps[(wr + g)     * FST + jt * 8 + pc1] = f2tf32(e1);
            Ps[(wr + g + 8) * FST + jt * 8 + pc0] = f2tf32(e2);
            Ps[(wr + g + 8) * FST + jt * 8 + pc1] = f2tf32(e3);
        }
        rs0 += __shfl_xor_sync(0xffffffffu, rs0, 1);
        rs0 += __shfl_xor_sync(0xffffffffu, rs0, 2);
        rs1 += __shfl_xor_sync(0xffffffffu, rs1, 1);
        rs1 += __shfl_xor_sync(0xffffffffu, rs1, 2);

        l0 = l0 * a0 + rs0;
        l1 = l1 * a1 + rs1;
        m0 = mn0; m1 = mn1;
        #pragma unroll
        for (int jt = 0; jt < 8; jt++) {
            o[jt][0] *= a0; o[jt][1] *= a0;
            o[jt][2] *= a1; o[jt][3] *= a1;
        }
        __syncthreads();   // P visible to the warp's own reads + pipeline

        // ---- O += P @ V ----
        #pragma unroll
        for (int s = 0; s < 8; s++) {
            const uint2 p0 = *(const uint2*)&Ps[(wr + g)     * FST + s * 8 + 2 * tg];
            const uint2 p1 = *(const uint2*)&Ps[(wr + g + 8) * FST + s * 8 + 2 * tg];
            const uint32_t pa[4] = {p0.x, p1.x, p0.y, p1.y};
            #pragma unroll
            for (int dt = 0; dt < 8; dt++) {
                const uint2 vb2 = *(const uint2*)&Vt[(dt * 8 + g) * FST + s * 8 + 2 * tg];
                const uint32_t vb[2] = {vb2.x, vb2.y};
                mma_tf32(o[dt], pa, vb);
            }
        }
    }

    // ---- Epilogue: normalize, write to [B, T, H*HD] ----
    const float i0 = 1.0f / l0, i1 = 1.0f / l1;
    const int bb = bh >> 4, h = bh & 15;
    const int row0 = q0 + wr + g, row1 = row0 + 8;
    #pragma unroll
    for (int dt = 0; dt < 8; dt++) {
        const int dcol = h * HD_ + dt * 8 + 2 * tg;
        *(float2*)&g_o[((size_t)bb * T_ + row0) * D_ + dcol] =
            make_float2(o[dt][0] * i0, o[dt][1] * i0);
        *(float2*)&g_o[((size_t)bb * T_ + row1) * D_ + dcol] =
            make_float2(o[dt][2] * i1, o[dt][3] * i1);
    }
}

// ---------------------------------------------------------------------------
extern "C" void kernel_launch(void* const* d_in, const int* in_sizes, int n_in,
                              void* d_out, int out_size)
{
    const float* x  = (const float*)d_in[0];
    const float* Wq = (const float*)d_in[1];
    const float* bq = (const float*)d_in[2];
    const float* Wk = (const float*)d_in[3];
    const float* bk = (const float*)d_in[4];
    const float* Wv = (const float*)d_in[5];
    const float* bv = (const float*)d_in[6];
    const float* Wo = (const float*)d_in[7];
    const float* bo = (const float*)d_in[8];
    float* out = (float*)d_out;

    cudaFuncSetAttribute(flash_tc, cudaFuncAttributeMaxDynamicSharedMemorySize,
                         FLASH_SMEM);

    dim3 gg(D_ / 128, MROWS / 128);          // (8, 64)
    gemm_tc<<<gg, 256>>>(x, Wq, bq, nullptr, 0);
    gemm_tc<<<gg, 256>>>(x, Wk, bk, nullptr, 1);
    gemm_tc<<<gg, 256>>>(x, Wv, bv, nullptr, 2);

    dim3 attn_grid(B_ * H_, T_ / FBr);       // (64, 16)
    flash_tc<<<attn_grid, 256, FLASH_SMEM>>>();

    gemm_tc<<<gg, 256>>>(nullptr, Wo, bo, out, 3);
}

// round 7
// speedup vs baseline: 2.3615x; 1.0142x over previous
#include <cuda_runtime.h>
#include <cstdint>

// Problem constants
constexpr int B_  = 4;
constexpr int T_  = 2048;
constexpr int D_  = 1024;
constexpr int H_  = 16;
constexpr int HD_ = 64;
constexpr int MROWS = B_ * T_;   // 8192
constexpr int KDIM  = D_;        // 1024

// Scratch (device globals: allocation-free)
__device__ float g_q[(size_t)B_ * H_ * T_ * HD_];
__device__ float g_k[(size_t)B_ * H_ * T_ * HD_];
__device__ float g_v[(size_t)B_ * H_ * T_ * HD_];
__device__ float g_o[(size_t)MROWS * D_];

// ---------------------------------------------------------------------------
// tf32 helpers (mma.sync path — plain sm_103 PTX target)
// ---------------------------------------------------------------------------
__device__ __forceinline__ uint32_t f2tf32(float f) {
    uint32_t u;
    asm("cvt.rna.tf32.f32 %0, %1;" : "=r"(u) : "f"(f));
    return u;
}

__device__ __forceinline__ void mma_tf32(float c[4], const uint32_t a[4],
                                         const uint32_t b[2]) {
    asm volatile(
        "mma.sync.aligned.m16n8k8.row.col.f32.tf32.tf32.f32 "
        "{%0,%1,%2,%3}, {%4,%5,%6,%7}, {%8,%9}, {%0,%1,%2,%3};"
        : "+f"(c[0]), "+f"(c[1]), "+f"(c[2]), "+f"(c[3])
        : "r"(a[0]), "r"(a[1]), "r"(a[2]), "r"(a[3]), "r"(b[0]), "r"(b[1]));
}

// ===========================================================================
// tf32 tensor-core GEMM (unchanged — passing at rel_err 5.6e-4)
// ===========================================================================
constexpr int BKF = 32;
constexpr int LDS_S = 36;

__global__ void __launch_bounds__(256)
gemm_tc(const float* __restrict__ Aext,
        const float* __restrict__ W,
        const float* __restrict__ bias,
        float* __restrict__ Yext,
        int mode)
{
    __shared__ uint32_t As[128 * LDS_S];
    __shared__ uint32_t Bs[128 * LDS_S];

    const float* A = (mode == 3) ? g_o : Aext;
    float* Y = (mode == 0) ? g_q : (mode == 1) ? g_k : (mode == 2) ? g_v : Yext;

    const int bn0 = blockIdx.x * 128;
    const int bm0 = blockIdx.y * 128;

    const int tid  = threadIdx.x;
    const int lane = tid & 31;
    const int wid  = tid >> 5;
    const int g    = lane >> 2;
    const int tg   = lane & 3;
    const int wm   = (wid >> 2) * 64;
    const int wn   = (wid & 3) * 32;

    float acc[4][4][4];
    #pragma unroll
    for (int i = 0; i < 4; i++)
        #pragma unroll
        for (int j = 0; j < 4; j++)
            #pragma unroll
            for (int r = 0; r < 4; r++) acc[i][j][r] = 0.f;

    const int lr4 = tid >> 3;
    const int lc4 = tid & 7;

    const float4* gA = (const float4*)(A + (size_t)(bm0 + lr4) * KDIM) + lc4;
    const float4* gB = (const float4*)(W + (size_t)(bn0 + lr4) * KDIM) + lc4;
    const int rowStep4 = 32 * (KDIM / 4);

    float4 ra[4], rb[4];
    #pragma unroll
    for (int i = 0; i < 4; i++) {
        ra[i] = gA[(size_t)i * rowStep4];
        rb[i] = gB[(size_t)i * rowStep4];
    }

    const int NK = KDIM / BKF;
    for (int kc = 0; kc < NK; kc++) {
        if (kc > 0) __syncthreads();
        #pragma unroll
        for (int i = 0; i < 4; i++) {
            const int s = (lr4 + i * 32) * LDS_S + lc4 * 4;
            As[s + 0] = f2tf32(ra[i].x); As[s + 1] = f2tf32(ra[i].y);
            As[s + 2] = f2tf32(ra[i].z); As[s + 3] = f2tf32(ra[i].w);
            Bs[s + 0] = f2tf32(rb[i].x); Bs[s + 1] = f2tf32(rb[i].y);
            Bs[s + 2] = f2tf32(rb[i].z); Bs[s + 3] = f2tf32(rb[i].w);
        }
        __syncthreads();

        if (kc + 1 < NK) {
            const int koff = (kc + 1) * (BKF / 4);
            #pragma unroll
            for (int i = 0; i < 4; i++) {
                ra[i] = gA[(size_t)i * rowStep4 + koff];
                rb[i] = gB[(size_t)i * rowStep4 + koff];
            }
        }

        #pragma unroll
        for (int s = 0; s < 4; s++) {
            uint32_t af[4][4];
            #pragma unroll
            for (int i = 0; i < 4; i++) {
                const int base = (wm + i * 16 + g) * LDS_S + s * 8 + tg;
                af[i][0] = As[base];
                af[i][1] = As[base + 8 * LDS_S];
                af[i][2] = As[base + 4];
                af[i][3] = As[base + 8 * LDS_S + 4];
            }
            uint32_t bf[4][2];
            #pragma unroll
            for (int j = 0; j < 4; j++) {
                const int base = (wn + j * 8 + g) * LDS_S + s * 8 + tg;
                bf[j][0] = Bs[base];
                bf[j][1] = Bs[base + 4];
            }
            #pragma unroll
            for (int i = 0; i < 4; i++)
                #pragma unroll
                for (int j = 0; j < 4; j++)
                    mma_tf32(acc[i][j], af[i], bf[j]);
        }
    }

    #pragma unroll
    for (int j = 0; j < 4; j++) {
        const int n = bn0 + wn + j * 8 + 2 * tg;
        const float bx = bias[n], by = bias[n + 1];
        #pragma unroll
        for (int i = 0; i < 4; i++) {
            const int m0 = bm0 + wm + i * 16 + g;
            float2 v0 = make_float2(acc[i][j][0] + bx, acc[i][j][1] + by);
            float2 v1 = make_float2(acc[i][j][2] + bx, acc[i][j][3] + by);
            if (mode < 3) {
                const int h = n >> 6, hd = n & (HD_ - 1);
                const int bb0 = m0 >> 11, t0 = m0 & (T_ - 1);
                const int m1 = m0 + 8;
                const int bb1 = m1 >> 11, t1 = m1 & (T_ - 1);
                *(float2*)&Y[(((size_t)bb0 * H_ + h) * T_ + t0) * HD_ + hd] = v0;
                *(float2*)&Y[(((size_t)bb1 * H_ + h) * T_ + t1) * HD_ + hd] = v1;
            } else {
                *(float2*)&Y[(size_t)m0 * D_ + n] = v0;
                *(float2*)&Y[(size_t)(m0 + 8) * D_ + n] = v1;
            }
        }
    }
}

// ===========================================================================
// Tensor-core flash attention v2 (tf32 mma.sync).
// R7 changes: (1) P round-trip is warp-private -> __syncwarp instead of
// __syncthreads; (2) double-buffered K/V smem with register prefetch of the
// next+1 tile (global latency hidden behind MMA phase); (3) one
// __syncthreads per key tile.
// ===========================================================================
constexpr int FBr = 128, FBc = 64;
constexpr int FST = 68;                          // smem row stride (words)
constexpr int KV_WORDS = 3 * 64 * FST;           // Khi+Klo+Vt per buffer
constexpr int OFF_PS = 2 * KV_WORDS;
constexpr int FLASH_SMEM = (6 * 64 + FBr) * FST * 4;   // 139264 B

__device__ __forceinline__ int permc(int c) {    // permute col within k8 step
    return ((c & 3) << 1) | (c >> 2);
}

__global__ void __launch_bounds__(256)
flash_tc()
{
    extern __shared__ uint32_t smw[];
    uint32_t* Ps  = smw + OFF_PS;
    float*    Psf = (float*)Ps;

    const int bh = blockIdx.x;
    const int q0 = blockIdx.y * FBr;
    const float* Qg = g_q + (size_t)bh * T_ * HD_;
    const float* Kg = g_k + (size_t)bh * T_ * HD_;
    const float* Vg = g_v + (size_t)bh * T_ * HD_;

    const int tid = threadIdx.x, lane = tid & 31, wid = tid >> 5;
    const int g = lane >> 2, tg = lane & 3;
    const int wr = wid * 16;

    // K/V global load mapping: thread covers rows r0+16i (i=0..3), float4
    // column c4. (64 rows x 16 float4 per tile.)
    const int r0 = tid >> 4;
    const int c4 = tid & 15;

    const float4* K4 = (const float4*)Kg + c4;
    const float4* V4 = (const float4*)Vg + c4;

    // ---- Stage Q (pre-scaled) into Ps, prefetch tile 0 ----
    #pragma unroll
    for (int i = 0; i < 8; i++) {
        const int idx = tid + i * 256;
        const int r = idx >> 4, qc4 = idx & 15;
        float4 q = *(const float4*)(Qg + (size_t)(q0 + r) * HD_ + qc4 * 4);
        float* d = Psf + r * FST + qc4 * 4;
        d[0] = q.x * 0.125f; d[1] = q.y * 0.125f;
        d[2] = q.z * 0.125f; d[3] = q.w * 0.125f;
    }

    float4 ra[4], rv[4];
    #pragma unroll
    for (int i = 0; i < 4; i++) {                 // tile 0
        ra[i] = K4[(size_t)(r0 + 16 * i) * 16];
        rv[i] = V4[(size_t)(r0 + 16 * i) * 16];
    }
    __syncthreads();

    // ---- Extract Q hi/lo A-fragments ----
    uint32_t qh[8][4], ql[8][4];
    #pragma unroll
    for (int s = 0; s < 8; s++) {
        float v[4];
        v[0] = Psf[(wr + g)     * FST + s * 8 + tg];
        v[1] = Psf[(wr + g + 8) * FST + s * 8 + tg];
        v[2] = Psf[(wr + g)     * FST + s * 8 + tg + 4];
        v[3] = Psf[(wr + g + 8) * FST + s * 8 + tg + 4];
        #pragma unroll
        for (int u = 0; u < 4; u++) {
            qh[s][u] = f2tf32(v[u]);
            ql[s][u] = f2tf32(v[u] - __uint_as_float(qh[s][u]));
        }
    }

    // ---- Stage tile 0 into buffer 0; prefetch tile 1 ----
    {
        uint32_t* Khi = smw;
        uint32_t* Klo = smw + 64 * FST;
        uint32_t* Vt  = smw + 2 * 64 * FST;
        #pragma unroll
        for (int i = 0; i < 4; i++) {
            const int r = r0 + 16 * i;
            const int dbase = c4 * 4;
            const float kf[4] = {ra[i].x, ra[i].y, ra[i].z, ra[i].w};
            const float vf[4] = {rv[i].x, rv[i].y, rv[i].z, rv[i].w};
            const int pj = (r & ~7) + permc(r & 7);
            #pragma unroll
            for (int u = 0; u < 4; u++) {
                const int d = dbase + u;
                const int pc = (d & ~7) + permc(d & 7);
                const uint32_t hi = f2tf32(kf[u]);
                Khi[r * FST + pc] = hi;
                Klo[r * FST + pc] = f2tf32(kf[u] - __uint_as_float(hi));
                Vt[d * FST + pj] = f2tf32(vf[u]);
            }
        }
        #pragma unroll
        for (int i = 0; i < 4; i++) {             // tile 1
            ra[i] = K4[(size_t)(64 + r0 + 16 * i) * 16];
            rv[i] = V4[(size_t)(64 + r0 + 16 * i) * 16];
        }
    }

    float o[8][4];
    #pragma unroll
    for (int j = 0; j < 8; j++)
        #pragma unroll
        for (int r = 0; r < 4; r++) o[j][r] = 0.f;
    float m0 = -1e30f, m1 = -1e30f, l0 = 0.f, l1 = 0.f;

    constexpr int NT = T_ / FBc;                  // 32
    for (int it = 0; it < NT; it++) {
        __syncthreads();  // buf[it&1] stores visible; buf[(it+1)&1] consumers done

        // ---- Stage regs (tile it+1) into the other buffer; prefetch it+2 ----
        if (it + 1 < NT) {
            uint32_t* buf = smw + ((it + 1) & 1) * KV_WORDS;
            uint32_t* Khi = buf;
            uint32_t* Klo = buf + 64 * FST;
            uint32_t* Vt  = buf + 2 * 64 * FST;
            #pragma unroll
            for (int i = 0; i < 4; i++) {
                const int r = r0 + 16 * i;
                const int dbase = c4 * 4;
                const float kf[4] = {ra[i].x, ra[i].y, ra[i].z, ra[i].w};
                const float vf[4] = {rv[i].x, rv[i].y, rv[i].z, rv[i].w};
                const int pj = (r & ~7) + permc(r & 7);
                #pragma unroll
                for (int u = 0; u < 4; u++) {
                    const int d = dbase + u;
                    const int pc = (d & ~7) + permc(d & 7);
                    const uint32_t hi = f2tf32(kf[u]);
                    Khi[r * FST + pc] = hi;
                    Klo[r * FST + pc] = f2tf32(kf[u] - __uint_as_float(hi));
                    Vt[d * FST + pj] = f2tf32(vf[u]);
                }
            }
            if (it + 2 < NT) {
                const size_t row = (size_t)(it + 2) * 64;
                #pragma unroll
                for (int i = 0; i < 4; i++) {
                    ra[i] = K4[(row + r0 + 16 * i) * 16];
                    rv[i] = V4[(row + r0 + 16 * i) * 16];
                }
            }
        }

        const uint32_t* buf = smw + (it & 1) * KV_WORDS;
        const uint32_t* Khi = buf;
        const uint32_t* Klo = buf + 64 * FST;
        const uint32_t* Vt  = buf + 2 * 64 * FST;

        // ---- S = Q @ K^T (split tf32) ----
        float sacc[8][4];
        #pragma unroll
        for (int j = 0; j < 8; j++)
            #pragma unroll
            for (int r = 0; r < 4; r++) sacc[j][r] = 0.f;

        #pragma unroll
        for (int s = 0; s < 8; s++) {
            #pragma unroll
            for (int jt = 0; jt < 8; jt++) {
                const uint2 kh2 = *(const uint2*)&Khi[(jt * 8 + g) * FST + s * 8 + 2 * tg];
                const uint2 kl2 = *(const uint2*)&Klo[(jt * 8 + g) * FST + s * 8 + 2 * tg];
                const uint32_t bhh[2] = {kh2.x, kh2.y};
                const uint32_t bll[2] = {kl2.x, kl2.y};
                mma_tf32(sacc[jt], qh[s], bhh);
                mma_tf32(sacc[jt], ql[s], bhh);
                mma_tf32(sacc[jt], qh[s], bll);
            }
        }

        // ---- Online softmax (rows g and g+8) ----
        float mx0 = -1e30f, mx1 = -1e30f;
        #pragma unroll
        for (int jt = 0; jt < 8; jt++) {
            mx0 = fmaxf(mx0, fmaxf(sacc[jt][0], sacc[jt][1]));
            mx1 = fmaxf(mx1, fmaxf(sacc[jt][2], sacc[jt][3]));
        }
        mx0 = fmaxf(mx0, __shfl_xor_sync(0xffffffffu, mx0, 1));
        mx0 = fmaxf(mx0, __shfl_xor_sync(0xffffffffu, mx0, 2));
        mx1 = fmaxf(mx1, __shfl_xor_sync(0xffffffffu, mx1, 1));
        mx1 = fmaxf(mx1, __shfl_xor_sync(0xffffffffu, mx1, 2));

        const float mn0 = fmaxf(m0, mx0), mn1 = fmaxf(m1, mx1);
        const float a0 = __expf(m0 - mn0), a1 = __expf(m1 - mn1);

        const int pc0 = permc(2 * tg);
        const int pc1 = permc(2 * tg + 1);
        float rs0 = 0.f, rs1 = 0.f;
        #pragma unroll
        for (int jt = 0; jt < 8; jt++) {
            const float e0 = __expf(sacc[jt][0] - mn0);
            const float e1 = __expf(sacc[jt][1] - mn0);
            const float e2 = __expf(sacc[jt][2] - mn1);
            const float e3 = __expf(sacc[jt][3] - mn1);
            rs0 += e0 + e1;
            rs1 += e2 + e3;
            Ps[(wr + g)     * FST + jt * 8 + pc0] = f2tf32(e0);
            Ps[(wr + g)     * FST + jt * 8 + pc1] = f2tf32(e1);
            Ps[(wr + g + 8) * FST + jt * 8 + pc0] = f2tf32(e2);
            Ps[(wr + g + 8) * FST + jt * 8 + pc1] = f2tf32(e3);
        }
        rs0 += __shfl_xor_sync(0xffffffffu, rs0, 1);
        rs0 += __shfl_xor_sync(0xffffffffu, rs0, 2);
        rs1 += __shfl_xor_sync(0xffffffffu, rs1, 1);
        rs1 += __shfl_xor_sync(0xffffffffu, rs1, 2);

        l0 = l0 * a0 + rs0;
        l1 = l1 * a1 + rs1;
        m0 = mn0; m1 = mn1;
        #pragma unroll
        for (int jt = 0; jt < 8; jt++) {
            o[jt][0] *= a0; o[jt][1] *= a0;
            o[jt][2] *= a1; o[jt][3] *= a1;
        }
        __syncwarp();   // P rows are warp-private: warp-level ordering only

        // ---- O += P @ V ----
        #pragma unroll
        for (int s = 0; s < 8; s++) {
            const uint2 p0 = *(const uint2*)&Ps[(wr + g)     * FST + s * 8 + 2 * tg];
            const uint2 p1 = *(const uint2*)&Ps[(wr + g + 8) * FST + s * 8 + 2 * tg];
            const uint32_t pa[4] = {p0.x, p1.x, p0.y, p1.y};
            #pragma unroll
            for (int dt = 0; dt < 8; dt++) {
                const uint2 vb2 = *(const uint2*)&Vt[(dt * 8 + g) * FST + s * 8 + 2 * tg];
                const uint32_t vb[2] = {vb2.x, vb2.y};
                mma_tf32(o[dt], pa, vb);
            }
        }
        __syncwarp();   // Ps reads done before next tile overwrites (warp-local)
    }

    // ---- Epilogue: normalize, write to [B, T, H*HD] ----
    const float i0 = 1.0f / l0, i1 = 1.0f / l1;
    const int bb = bh >> 4, h = bh & 15;
    const int row0 = q0 + wr + g, row1 = row0 + 8;
    #pragma unroll
    for (int dt = 0; dt < 8; dt++) {
        const int dcol = h * HD_ + dt * 8 + 2 * tg;
        *(float2*)&g_o[((size_t)bb * T_ + row0) * D_ + dcol] =
            make_float2(o[dt][0] * i0, o[dt][1] * i0);
        *(float2*)&g_o[((size_t)bb * T_ + row1) * D_ + dcol] =
            make_float2(o[dt][2] * i1, o[dt][3] * i1);
    }
}

// ---------------------------------------------------------------------------
extern "C" void kernel_launch(void* const* d_in, const int* in_sizes, int n_in,
                              void* d_out, int out_size)
{
    const float* x  = (const float*)d_in[0];
    const float* Wq = (const float*)d_in[1];
    const float* bq = (const float*)d_in[2];
    const float* Wk = (const float*)d_in[3];
    const float* bk = (const float*)d_in[4];
    const float* Wv = (const float*)d_in[5];
    const float* bv = (const float*)d_in[6];
    const float* Wo = (const float*)d_in[7];
    const float* bo = (const float*)d_in[8];
    float* out = (float*)d_out;

    cudaFuncSetAttribute(flash_tc, cudaFuncAttributeMaxDynamicSharedMemorySize,
                         FLASH_SMEM);

    dim3 gg(D_ / 128, MROWS / 128);          // (8, 64)
    gemm_tc<<<gg, 256>>>(x, Wq, bq, nullptr, 0);
    gemm_tc<<<gg, 256>>>(x, Wk, bk, nullptr, 1);
    gemm_tc<<<gg, 256>>>(x, Wv, bv, nullptr, 2);

    dim3 attn_grid(B_ * H_, T_ / FBr);       // (64, 16)
    flash_tc<<<attn_grid, 256, FLASH_SMEM>>>();

    gemm_tc<<<gg, 256>>>(nullptr, Wo, bo, out, 3);
}

// round 10
// speedup vs baseline: 3.5787x; 1.5154x over previous
#include <cuda_runtime.h>
#include <cstdint>

// Problem constants
constexpr int B_  = 4;
constexpr int T_  = 2048;
constexpr int D_  = 1024;
constexpr int H_  = 16;
constexpr int HD_ = 64;
constexpr int MROWS = B_ * T_;   // 8192
constexpr int KDIM  = D_;        // 1024

// Scratch (device globals: allocation-free)
__device__ float g_q[(size_t)B_ * H_ * T_ * HD_];
__device__ float g_k[(size_t)B_ * H_ * T_ * HD_];
__device__ float g_v[(size_t)B_ * H_ * T_ * HD_];
__device__ float g_o[(size_t)MROWS * D_];

// ---------------------------------------------------------------------------
// tf32 helpers (mma.sync path — plain sm_103 PTX target)
// ---------------------------------------------------------------------------
__device__ __forceinline__ uint32_t f2tf32(float f) {
    uint32_t u;
    asm("cvt.rna.tf32.f32 %0, %1;" : "=r"(u) : "f"(f));
    return u;
}

__device__ __forceinline__ void mma_tf32(float c[4], const uint32_t a[4],
                                         const uint32_t b[2]) {
    asm volatile(
        "mma.sync.aligned.m16n8k8.row.col.f32.tf32.tf32.f32 "
        "{%0,%1,%2,%3}, {%4,%5,%6,%7}, {%8,%9}, {%0,%1,%2,%3};"
        : "+f"(c[0]), "+f"(c[1]), "+f"(c[2]), "+f"(c[3])
        : "r"(a[0]), "r"(a[1]), "r"(a[2]), "r"(a[3]), "r"(b[0]), "r"(b[1]));
}

// ===========================================================================
// tf32 tensor-core GEMM (unchanged — passing at rel_err 5.6e-4)
// ===========================================================================
constexpr int BKF = 32;
constexpr int LDS_S = 36;

__global__ void __launch_bounds__(256)
gemm_tc(const float* __restrict__ Aext,
        const float* __restrict__ W,
        const float* __restrict__ bias,
        float* __restrict__ Yext,
        int mode)
{
    __shared__ uint32_t As[128 * LDS_S];
    __shared__ uint32_t Bs[128 * LDS_S];

    const float* A = (mode == 3) ? g_o : Aext;
    float* Y = (mode == 0) ? g_q : (mode == 1) ? g_k : (mode == 2) ? g_v : Yext;

    const int bn0 = blockIdx.x * 128;
    const int bm0 = blockIdx.y * 128;

    const int tid  = threadIdx.x;
    const int lane = tid & 31;
    const int wid  = tid >> 5;
    const int g    = lane >> 2;
    const int tg   = lane & 3;
    const int wm   = (wid >> 2) * 64;
    const int wn   = (wid & 3) * 32;

    float acc[4][4][4];
    #pragma unroll
    for (int i = 0; i < 4; i++)
        #pragma unroll
        for (int j = 0; j < 4; j++)
            #pragma unroll
            for (int r = 0; r < 4; r++) acc[i][j][r] = 0.f;

    const int lr4 = tid >> 3;
    const int lc4 = tid & 7;

    const float4* gA = (const float4*)(A + (size_t)(bm0 + lr4) * KDIM) + lc4;
    const float4* gB = (const float4*)(W + (size_t)(bn0 + lr4) * KDIM) + lc4;
    const int rowStep4 = 32 * (KDIM / 4);

    float4 ra[4], rb[4];
    #pragma unroll
    for (int i = 0; i < 4; i++) {
        ra[i] = gA[(size_t)i * rowStep4];
        rb[i] = gB[(size_t)i * rowStep4];
    }

    const int NK = KDIM / BKF;
    for (int kc = 0; kc < NK; kc++) {
        if (kc > 0) __syncthreads();
        #pragma unroll
        for (int i = 0; i < 4; i++) {
            const int s = (lr4 + i * 32) * LDS_S + lc4 * 4;
            As[s + 0] = f2tf32(ra[i].x); As[s + 1] = f2tf32(ra[i].y);
            As[s + 2] = f2tf32(ra[i].z); As[s + 3] = f2tf32(ra[i].w);
            Bs[s + 0] = f2tf32(rb[i].x); Bs[s + 1] = f2tf32(rb[i].y);
            Bs[s + 2] = f2tf32(rb[i].z); Bs[s + 3] = f2tf32(rb[i].w);
        }
        __syncthreads();

        if (kc + 1 < NK) {
            const int koff = (kc + 1) * (BKF / 4);
            #pragma unroll
            for (int i = 0; i < 4; i++) {
                ra[i] = gA[(size_t)i * rowStep4 + koff];
                rb[i] = gB[(size_t)i * rowStep4 + koff];
            }
        }

        #pragma unroll
        for (int s = 0; s < 4; s++) {
            uint32_t af[4][4];
            #pragma unroll
            for (int i = 0; i < 4; i++) {
                const int base = (wm + i * 16 + g) * LDS_S + s * 8 + tg;
                af[i][0] = As[base];
                af[i][1] = As[base + 8 * LDS_S];
                af[i][2] = As[base + 4];
                af[i][3] = As[base + 8 * LDS_S + 4];
            }
            uint32_t bf[4][2];
            #pragma unroll
            for (int j = 0; j < 4; j++) {
                const int base = (wn + j * 8 + g) * LDS_S + s * 8 + tg;
                bf[j][0] = Bs[base];
                bf[j][1] = Bs[base + 4];
            }
            #pragma unroll
            for (int i = 0; i < 4; i++)
                #pragma unroll
                for (int j = 0; j < 4; j++)
                    mma_tf32(acc[i][j], af[i], bf[j]);
        }
    }

    #pragma unroll
    for (int j = 0; j < 4; j++) {
        const int n = bn0 + wn + j * 8 + 2 * tg;
        const float bx = bias[n], by = bias[n + 1];
        #pragma unroll
        for (int i = 0; i < 4; i++) {
            const int m0 = bm0 + wm + i * 16 + g;
            float2 v0 = make_float2(acc[i][j][0] + bx, acc[i][j][1] + by);
            float2 v1 = make_float2(acc[i][j][2] + bx, acc[i][j][3] + by);
            if (mode < 3) {
                const int h = n >> 6, hd = n & (HD_ - 1);
                const int bb0 = m0 >> 11, t0 = m0 & (T_ - 1);
                const int m1 = m0 + 8;
                const int bb1 = m1 >> 11, t1 = m1 & (T_ - 1);
                *(float2*)&Y[(((size_t)bb0 * H_ + h) * T_ + t0) * HD_ + hd] = v0;
                *(float2*)&Y[(((size_t)bb1 * H_ + h) * T_ + t1) * HD_ + hd] = v1;
            } else {
                *(float2*)&Y[(size_t)m0 * D_ + n] = v0;
                *(float2*)&Y[(size_t)(m0 + 8) * D_ + n] = v1;
            }
        }
    }
}

// ===========================================================================
// Tensor-core flash attention v3 (tf32 mma.sync), smem-traffic-minimized.
// R8: (1) K-lo dropped (Q-side hi/lo split only): -128KB/tile reads, -1/3 QK
//     MMAs. (2) P never hits smem: per-k8-group key permutation
//     (slot tg <-> key 2tg, slot tg+4 <-> key 2tg+1) makes the S-accumulator
//     registers the PV A-fragment directly, with V stored NATURALLY
//     (key-major) and read as 2x LDS.32 (same wavefronts as LDS.64).
// (3) Khi stride 72 / Vs stride 68: conflict-free fragment loads.
// ===========================================================================
constexpr int FBr = 128, FBc = 64;
constexpr int FST_K = 72;                        // Khi row stride (words)
constexpr int FST_V = 68;                        // Vs  row stride (words)
constexpr int KHI_WORDS = 64 * FST_K;            // 4608
constexpr int BUF_WORDS = KHI_WORDS + 64 * FST_V; // 8960 per buffer
constexpr int QST = 65;                          // Q staging stride (in buf 1)
constexpr int FLASH_SMEM = 2 * BUF_WORDS * 4;    // 71680 B

__device__ __forceinline__ int permc(int c) {    // permute col within k8 step
    return ((c & 3) << 1) | (c >> 2);
}

__global__ void __launch_bounds__(256)
flash_tc()
{
    extern __shared__ uint32_t smw[];

    const int bh = blockIdx.x;
    const int q0 = blockIdx.y * FBr;
    const float* Qg = g_q + (size_t)bh * T_ * HD_;
    const float* Kg = g_k + (size_t)bh * T_ * HD_;
    const float* Vg = g_v + (size_t)bh * T_ * HD_;

    const int tid = threadIdx.x, lane = tid & 31, wid = tid >> 5;
    const int g = lane >> 2, tg = lane & 3;
    const int wr = wid * 16;

    // K/V global load mapping: rows r0+16i (i=0..3), float4 column c4.
    const int r0 = tid >> 4;
    const int c4 = tid & 15;

    const float4* K4 = (const float4*)Kg + c4;
    const float4* V4 = (const float4*)Vg + c4;

    // ---- Stage Q (pre-scaled) into buffer-1 region; prefetch tile 0 ----
    float* Qst = (float*)(smw + BUF_WORDS);
    #pragma unroll
    for (int i = 0; i < 8; i++) {
        const int idx = tid + i * 256;
        const int r = idx >> 4, qc4 = idx & 15;
        float4 q = *(const float4*)(Qg + (size_t)(q0 + r) * HD_ + qc4 * 4);
        float* d = Qst + r * QST + qc4 * 4;
        d[0] = q.x * 0.125f; d[1] = q.y * 0.125f;
        d[2] = q.z * 0.125f; d[3] = q.w * 0.125f;
    }

    float4 ra[4], rv[4];
    #pragma unroll
    for (int i = 0; i < 4; i++) {                 // tile 0
        ra[i] = K4[(size_t)(r0 + 16 * i) * 16];
        rv[i] = V4[(size_t)(r0 + 16 * i) * 16];
    }
    __syncthreads();

    // ---- Extract Q hi/lo A-fragments ----
    uint32_t qh[8][4], ql[8][4];
    #pragma unroll
    for (int s = 0; s < 8; s++) {
        float v[4];
        v[0] = Qst[(wr + g)     * QST + s * 8 + tg];
        v[1] = Qst[(wr + g + 8) * QST + s * 8 + tg];
        v[2] = Qst[(wr + g)     * QST + s * 8 + tg + 4];
        v[3] = Qst[(wr + g + 8) * QST + s * 8 + tg + 4];
        #pragma unroll
        for (int u = 0; u < 4; u++) {
            qh[s][u] = f2tf32(v[u]);
            ql[s][u] = f2tf32(v[u] - __uint_as_float(qh[s][u]));
        }
    }
    __syncthreads();   // all Q reads done before buffer staging overwrites

    // ---- Stage tile 0 into buffer 0; prefetch tile 1 ----
    {
        uint32_t* Khi = smw;
        uint32_t* Vs  = smw + KHI_WORDS;
        #pragma unroll
        for (int i = 0; i < 4; i++) {
            const int r = r0 + 16 * i;
            const int dbase = c4 * 4;
            const float kf[4] = {ra[i].x, ra[i].y, ra[i].z, ra[i].w};
            #pragma unroll
            for (int u = 0; u < 4; u++) {
                const int d = dbase + u;
                Khi[r * FST_K + (d & ~7) + permc(d & 7)] = f2tf32(kf[u]);
            }
            uint4 vw;
            vw.x = f2tf32(rv[i].x); vw.y = f2tf32(rv[i].y);
            vw.z = f2tf32(rv[i].z); vw.w = f2tf32(rv[i].w);
            *(uint4*)&Vs[r * FST_V + dbase] = vw;
        }
        #pragma unroll
        for (int i = 0; i < 4; i++) {             // tile 1
            ra[i] = K4[(size_t)(64 + r0 + 16 * i) * 16];
            rv[i] = V4[(size_t)(64 + r0 + 16 * i) * 16];
        }
    }

    float o[8][4];
    #pragma unroll
    for (int j = 0; j < 8; j++)
        #pragma unroll
        for (int r = 0; r < 4; r++) o[j][r] = 0.f;
    float m0 = -1e30f, m1 = -1e30f, l0 = 0.f, l1 = 0.f;

    constexpr int NT = T_ / FBc;                  // 32
    for (int it = 0; it < NT; it++) {
        __syncthreads();

        // ---- Stage regs (tile it+1) into other buffer; prefetch it+2 ----
        if (it + 1 < NT) {
            uint32_t* buf = smw + ((it + 1) & 1) * BUF_WORDS;
            uint32_t* Khi = buf;
            uint32_t* Vs  = buf + KHI_WORDS;
            #pragma unroll
            for (int i = 0; i < 4; i++) {
                const int r = r0 + 16 * i;
                const int dbase = c4 * 4;
                const float kf[4] = {ra[i].x, ra[i].y, ra[i].z, ra[i].w};
                #pragma unroll
                for (int u = 0; u < 4; u++) {
                    const int d = dbase + u;
                    Khi[r * FST_K + (d & ~7) + permc(d & 7)] = f2tf32(kf[u]);
                }
                uint4 vw;
                vw.x = f2tf32(rv[i].x); vw.y = f2tf32(rv[i].y);
                vw.z = f2tf32(rv[i].z); vw.w = f2tf32(rv[i].w);
                *(uint4*)&Vs[r * FST_V + dbase] = vw;
            }
            if (it + 2 < NT) {
                const size_t row = (size_t)(it + 2) * 64;
                #pragma unroll
                for (int i = 0; i < 4; i++) {
                    ra[i] = K4[(row + r0 + 16 * i) * 16];
                    rv[i] = V4[(row + r0 + 16 * i) * 16];
                }
            }
        }

        const uint32_t* buf = smw + (it & 1) * BUF_WORDS;
        const uint32_t* Khi = buf;
        const uint32_t* Vs  = buf + KHI_WORDS;

        // ---- S = Q @ K^T (Q hi/lo split, K single tf32) ----
        float sacc[8][4];
        #pragma unroll
        for (int j = 0; j < 8; j++)
            #pragma unroll
            for (int r = 0; r < 4; r++) sacc[j][r] = 0.f;

        #pragma unroll
        for (int s = 0; s < 8; s++) {
            #pragma unroll
            for (int jt = 0; jt < 8; jt++) {
                const uint2 kh2 = *(const uint2*)&Khi[(jt * 8 + g) * FST_K + s * 8 + 2 * tg];
                const uint32_t bhh[2] = {kh2.x, kh2.y};
                mma_tf32(sacc[jt], qh[s], bhh);
                mma_tf32(sacc[jt], ql[s], bhh);
            }
        }

        // ---- Online softmax (rows g and g+8); e's stay in sacc regs ----
        float mx0 = -1e30f, mx1 = -1e30f;
        #pragma unroll
        for (int jt = 0; jt < 8; jt++) {
            mx0 = fmaxf(mx0, fmaxf(sacc[jt][0], sacc[jt][1]));
            mx1 = fmaxf(mx1, fmaxf(sacc[jt][2], sacc[jt][3]));
        }
        mx0 = fmaxf(mx0, __shfl_xor_sync(0xffffffffu, mx0, 1));
        mx0 = fmaxf(mx0, __shfl_xor_sync(0xffffffffu, mx0, 2));
        mx1 = fmaxf(mx1, __shfl_xor_sync(0xffffffffu, mx1, 1));
        mx1 = fmaxf(mx1, __shfl_xor_sync(0xffffffffu, mx1, 2));

        const float mn0 = fmaxf(m0, mx0), mn1 = fmaxf(m1, mx1);
        const float a0 = __expf(m0 - mn0), a1 = __expf(m1 - mn1);

        float rs0 = 0.f, rs1 = 0.f;
        #pragma unroll
        for (int jt = 0; jt < 8; jt++) {
            sacc[jt][0] = __expf(sacc[jt][0] - mn0);
            sacc[jt][1] = __expf(sacc[jt][1] - mn0);
            sacc[jt][2] = __expf(sacc[jt][2] - mn1);
            sacc[jt][3] = __expf(sacc[jt][3] - mn1);
            rs0 += sacc[jt][0] + sacc[jt][1];
            rs1 += sacc[jt][2] + sacc[jt][3];
        }
        rs0 += __shfl_xor_sync(0xffffffffu, rs0, 1);
        rs0 += __shfl_xor_sync(0xffffffffu, rs0, 2);
        rs1 += __shfl_xor_sync(0xffffffffu, rs1, 1);
        rs1 += __shfl_xor_sync(0xffffffffu, rs1, 2);

        l0 = l0 * a0 + rs0;
        l1 = l1 * a1 + rs1;
        m0 = mn0; m1 = mn1;
        #pragma unroll
        for (int jt = 0; jt < 8; jt++) {
            o[jt][0] *= a0; o[jt][1] *= a0;
            o[jt][2] *= a1; o[jt][3] *= a1;
        }

        // ---- O += P @ V : P direct from registers (permuted key slots).
        // slot tg <-> key 2tg, slot tg+4 <-> key 2tg+1; V natural layout.
        #pragma unroll
        for (int jt = 0; jt < 8; jt++) {
            const uint32_t pa[4] = {f2tf32(sacc[jt][0]), f2tf32(sacc[jt][2]),
                                    f2tf32(sacc[jt][1]), f2tf32(sacc[jt][3])};
            const uint32_t* v0row = &Vs[(jt * 8 + 2 * tg)     * FST_V + g];
            const uint32_t* v1row = &Vs[(jt * 8 + 2 * tg + 1) * FST_V + g];
            #pragma unroll
            for (int dt = 0; dt < 8; dt++) {
                const uint32_t vb[2] = {v0row[dt * 8], v1row[dt * 8]};
                mma_tf32(o[dt], pa, vb);
            }
        }
    }

    // ---- Epilogue: normalize, write to [B, T, H*HD] ----
    const float i0 = 1.0f / l0, i1 = 1.0f / l1;
    const int bb = bh >> 4, h = bh & 15;
    const int row0 = q0 + wr + g, row1 = row0 + 8;
    #pragma unroll
    for (int dt = 0; dt < 8; dt++) {
        const int dcol = h * HD_ + dt * 8 + 2 * tg;
        *(float2*)&g_o[((size_t)bb * T_ + row0) * D_ + dcol] =
            make_float2(o[dt][0] * i0, o[dt][1] * i0);
        *(float2*)&g_o[((size_t)bb * T_ + row1) * D_ + dcol] =
            make_float2(o[dt][2] * i1, o[dt][3] * i1);
    }
}

// ---------------------------------------------------------------------------
extern "C" void kernel_launch(void* const* d_in, const int* in_sizes, int n_in,
                              void* d_out, int out_size)
{
    const float* x  = (const float*)d_in[0];
    const float* Wq = (const float*)d_in[1];
    const float* bq = (const float*)d_in[2];
    const float* Wk = (const float*)d_in[3];
    const float* bk = (const float*)d_in[4];
    const float* Wv = (const float*)d_in[5];
    const float* bv = (const float*)d_in[6];
    const float* Wo = (const float*)d_in[7];
    const float* bo = (const float*)d_in[8];
    float* out = (float*)d_out;

    cudaFuncSetAttribute(flash_tc, cudaFuncAttributeMaxDynamicSharedMemorySize,
                         FLASH_SMEM);

    dim3 gg(D_ / 128, MROWS / 128);          // (8, 64)
    gemm_tc<<<gg, 256>>>(x, Wq, bq, nullptr, 0);
    gemm_tc<<<gg, 256>>>(x, Wk, bk, nullptr, 1);
    gemm_tc<<<gg, 256>>>(x, Wv, bv, nullptr, 2);

    dim3 attn_grid(B_ * H_, T_ / FBr);       // (64, 16)
    flash_tc<<<attn_grid, 256, FLASH_SMEM>>>();

    gemm_tc<<<gg, 256>>>(nullptr, Wo, bo, out, 3);
}

// round 13
// speedup vs baseline: 4.0260x; 1.1250x over previous
#include <cuda_runtime.h>
#include <cstdint>

// Problem constants
constexpr int B_  = 4;
constexpr int T_  = 2048;
constexpr int D_  = 1024;
constexpr int H_  = 16;
constexpr int HD_ = 64;
constexpr int MROWS = B_ * T_;   // 8192
constexpr int KDIM  = D_;        // 1024

// Scratch (device globals: allocation-free)
__device__ float g_q[(size_t)B_ * H_ * T_ * HD_];
__device__ float g_k[(size_t)B_ * H_ * T_ * HD_];
__device__ float g_v[(size_t)B_ * H_ * T_ * HD_];
__device__ float g_o[(size_t)MROWS * D_];

// ---------------------------------------------------------------------------
// tf32 helpers (mma.sync path — plain sm_103 PTX target)
// ---------------------------------------------------------------------------
__device__ __forceinline__ uint32_t f2tf32(float f) {
    uint32_t u;
    asm("cvt.rna.tf32.f32 %0, %1;" : "=r"(u) : "f"(f));
    return u;
}

__device__ __forceinline__ void mma_tf32(float c[4], const uint32_t a[4],
                                         const uint32_t b[2]) {
    asm volatile(
        "mma.sync.aligned.m16n8k8.row.col.f32.tf32.tf32.f32 "
        "{%0,%1,%2,%3}, {%4,%5,%6,%7}, {%8,%9}, {%0,%1,%2,%3};"
        : "+f"(c[0]), "+f"(c[1]), "+f"(c[2]), "+f"(c[3])
        : "r"(a[0]), "r"(a[1]), "r"(a[2]), "r"(a[3]), "r"(b[0]), "r"(b[1]));
}

// ===========================================================================
// tf32 tensor-core GEMM, R11: double-buffered smem, ONE barrier per K chunk
// (stores to buf[(kc+1)&1] are ordered against iter-(kc-1) reads by the
// iter-kc barrier; reads of buf[kc&1] ordered against iter-(kc-1) stores by
// the same barrier).
// ===========================================================================
constexpr int BKF = 32;
constexpr int LDS_S = 36;
constexpr int GBUFW = 2 * 128 * LDS_S;            // As+Bs words per buffer
constexpr int GEMM_SMEM = 2 * GBUFW * 4;          // 73728 B

__global__ void __launch_bounds__(256)
gemm_tc(const float* __restrict__ Aext,
        const float* __restrict__ W,
        const float* __restrict__ bias,
        float* __restrict__ Yext,
        int mode)
{
    extern __shared__ uint32_t gsm[];

    const float* A = (mode == 3) ? g_o : Aext;
    float* Y = (mode == 0) ? g_q : (mode == 1) ? g_k : (mode == 2) ? g_v : Yext;

    const int bn0 = blockIdx.x * 128;
    const int bm0 = blockIdx.y * 128;

    const int tid  = threadIdx.x;
    const int lane = tid & 31;
    const int wid  = tid >> 5;
    const int g    = lane >> 2;
    const int tg   = lane & 3;
    const int wm   = (wid >> 2) * 64;
    const int wn   = (wid & 3) * 32;

    float acc[4][4][4];
    #pragma unroll
    for (int i = 0; i < 4; i++)
        #pragma unroll
        for (int j = 0; j < 4; j++)
            #pragma unroll
            for (int r = 0; r < 4; r++) acc[i][j][r] = 0.f;

    const int lr4 = tid >> 3;
    const int lc4 = tid & 7;

    const float4* gA = (const float4*)(A + (size_t)(bm0 + lr4) * KDIM) + lc4;
    const float4* gB = (const float4*)(W + (size_t)(bn0 + lr4) * KDIM) + lc4;
    const int rowStep4 = 32 * (KDIM / 4);

    float4 ra[4], rb[4];

    auto stage = [&](int p) {
        uint32_t* As = gsm + p * GBUFW;
        uint32_t* Bs = As + 128 * LDS_S;
        #pragma unroll
        for (int i = 0; i < 4; i++) {
            const int s = (lr4 + i * 32) * LDS_S + lc4 * 4;
            As[s + 0] = f2tf32(ra[i].x); As[s + 1] = f2tf32(ra[i].y);
            As[s + 2] = f2tf32(ra[i].z); As[s + 3] = f2tf32(ra[i].w);
            Bs[s + 0] = f2tf32(rb[i].x); Bs[s + 1] = f2tf32(rb[i].y);
            Bs[s + 2] = f2tf32(rb[i].z); Bs[s + 3] = f2tf32(rb[i].w);
        }
    };
    auto fetch = [&](int kc) {
        const int koff = kc * (BKF / 4);
        #pragma unroll
        for (int i = 0; i < 4; i++) {
            ra[i] = gA[(size_t)i * rowStep4 + koff];
            rb[i] = gB[(size_t)i * rowStep4 + koff];
        }
    };

    const int NK = KDIM / BKF;   // 32

    // Prologue: chunk 0 staged to buf0; chunk 1 in registers.
    fetch(0);
    stage(0);
    fetch(1);

    for (int kc = 0; kc < NK; kc++) {
        __syncthreads();
        if (kc + 1 < NK) {
            stage((kc + 1) & 1);
            if (kc + 2 < NK) fetch(kc + 2);
        }

        const uint32_t* As = gsm + (kc & 1) * GBUFW;
        const uint32_t* Bs = As + 128 * LDS_S;

        #pragma unroll
        for (int s = 0; s < 4; s++) {
            uint32_t af[4][4];
            #pragma unroll
            for (int i = 0; i < 4; i++) {
                const int base = (wm + i * 16 + g) * LDS_S + s * 8 + tg;
                af[i][0] = As[base];
                af[i][1] = As[base + 8 * LDS_S];
                af[i][2] = As[base + 4];
                af[i][3] = As[base + 8 * LDS_S + 4];
            }
            uint32_t bf[4][2];
            #pragma unroll
            for (int j = 0; j < 4; j++) {
                const int base = (wn + j * 8 + g) * LDS_S + s * 8 + tg;
                bf[j][0] = Bs[base];
                bf[j][1] = Bs[base + 4];
            }
            #pragma unroll
            for (int i = 0; i < 4; i++)
                #pragma unroll
                for (int j = 0; j < 4; j++)
                    mma_tf32(acc[i][j], af[i], bf[j]);
        }
    }

    #pragma unroll
    for (int j = 0; j < 4; j++) {
        const int n = bn0 + wn + j * 8 + 2 * tg;
        const float bx = bias[n], by = bias[n + 1];
        #pragma unroll
        for (int i = 0; i < 4; i++) {
            const int m0 = bm0 + wm + i * 16 + g;
            float2 v0 = make_float2(acc[i][j][0] + bx, acc[i][j][1] + by);
            float2 v1 = make_float2(acc[i][j][2] + bx, acc[i][j][3] + by);
            if (mode < 3) {
                const int h = n >> 6, hd = n & (HD_ - 1);
                const int bb0 = m0 >> 11, t0 = m0 & (T_ - 1);
                const int m1 = m0 + 8;
                const int bb1 = m1 >> 11, t1 = m1 & (T_ - 1);
                *(float2*)&Y[(((size_t)bb0 * H_ + h) * T_ + t0) * HD_ + hd] = v0;
                *(float2*)&Y[(((size_t)bb1 * H_ + h) * T_ + t1) * HD_ + hd] = v1;
            } else {
                *(float2*)&Y[(size_t)m0 * D_ + n] = v0;
                *(float2*)&Y[(size_t)(m0 + 8) * D_ + n] = v1;
            }
        }
    }
}

// ===========================================================================
// Tensor-core flash attention v4 (tf32 mma.sync).
// R11: Q-lo split dropped (single tf32 QK^T) — evidence: K-lo drop moved
// rel_err only +2.5e-5, Q side is symmetric. QK MMAs halve; -32 regs.
// P stays in registers (permuted key slots), V natural layout (R8).
// ===========================================================================
constexpr int FBr = 128, FBc = 64;
constexpr int FST_K = 72;                        // Khi row stride (words)
constexpr int FST_V = 68;                        // Vs  row stride (words)
constexpr int KHI_WORDS = 64 * FST_K;            // 4608
constexpr int BUF_WORDS = KHI_WORDS + 64 * FST_V; // 8960 per buffer
constexpr int QST = 65;                          // Q staging stride (in buf 1)
constexpr int FLASH_SMEM = 2 * BUF_WORDS * 4;    // 71680 B

__device__ __forceinline__ int permc(int c) {    // permute col within k8 step
    return ((c & 3) << 1) | (c >> 2);
}

__global__ void __launch_bounds__(256)
flash_tc()
{
    extern __shared__ uint32_t smw[];

    const int bh = blockIdx.x;
    const int q0 = blockIdx.y * FBr;
    const float* Qg = g_q + (size_t)bh * T_ * HD_;
    const float* Kg = g_k + (size_t)bh * T_ * HD_;
    const float* Vg = g_v + (size_t)bh * T_ * HD_;

    const int tid = threadIdx.x, lane = tid & 31, wid = tid >> 5;
    const int g = lane >> 2, tg = lane & 3;
    const int wr = wid * 16;

    // K/V global load mapping: rows r0+16i (i=0..3), float4 column c4.
    const int r0 = tid >> 4;
    const int c4 = tid & 15;

    const float4* K4 = (const float4*)Kg + c4;
    const float4* V4 = (const float4*)Vg + c4;

    // ---- Stage Q (pre-scaled) into buffer-1 region; prefetch tile 0 ----
    float* Qst = (float*)(smw + BUF_WORDS);
    #pragma unroll
    for (int i = 0; i < 8; i++) {
        const int idx = tid + i * 256;
        const int r = idx >> 4, qc4 = idx & 15;
        float4 q = *(const float4*)(Qg + (size_t)(q0 + r) * HD_ + qc4 * 4);
        float* d = Qst + r * QST + qc4 * 4;
        d[0] = q.x * 0.125f; d[1] = q.y * 0.125f;
        d[2] = q.z * 0.125f; d[3] = q.w * 0.125f;
    }

    float4 ra[4], rv[4];
    #pragma unroll
    for (int i = 0; i < 4; i++) {                 // tile 0
        ra[i] = K4[(size_t)(r0 + 16 * i) * 16];
        rv[i] = V4[(size_t)(r0 + 16 * i) * 16];
    }
    __syncthreads();

    // ---- Extract Q A-fragments (single tf32) ----
    uint32_t qh[8][4];
    #pragma unroll
    for (int s = 0; s < 8; s++) {
        qh[s][0] = f2tf32(Qst[(wr + g)     * QST + s * 8 + tg]);
        qh[s][1] = f2tf32(Qst[(wr + g + 8) * QST + s * 8 + tg]);
        qh[s][2] = f2tf32(Qst[(wr + g)     * QST + s * 8 + tg + 4]);
        qh[s][3] = f2tf32(Qst[(wr + g + 8) * QST + s * 8 + tg + 4]);
    }
    __syncthreads();   // all Q reads done before buffer staging overwrites

    // ---- Stage tile 0 into buffer 0; prefetch tile 1 ----
    {
        uint32_t* Khi = smw;
        uint32_t* Vs  = smw + KHI_WORDS;
        #pragma unroll
        for (int i = 0; i < 4; i++) {
            const int r = r0 + 16 * i;
            const int dbase = c4 * 4;
            const float kf[4] = {ra[i].x, ra[i].y, ra[i].z, ra[i].w};
            #pragma unroll
            for (int u = 0; u < 4; u++) {
                const int d = dbase + u;
                Khi[r * FST_K + (d & ~7) + permc(d & 7)] = f2tf32(kf[u]);
            }
            uint4 vw;
            vw.x = f2tf32(rv[i].x); vw.y = f2tf32(rv[i].y);
            vw.z = f2tf32(rv[i].z); vw.w = f2tf32(rv[i].w);
            *(uint4*)&Vs[r * FST_V + dbase] = vw;
        }
        #pragma unroll
        for (int i = 0; i < 4; i++) {             // tile 1
            ra[i] = K4[(size_t)(64 + r0 + 16 * i) * 16];
            rv[i] = V4[(size_t)(64 + r0 + 16 * i) * 16];
        }
    }

    float o[8][4];
    #pragma unroll
    for (int j = 0; j < 8; j++)
        #pragma unroll
        for (int r = 0; r < 4; r++) o[j][r] = 0.f;
    float m0 = -1e30f, m1 = -1e30f, l0 = 0.f, l1 = 0.f;

    constexpr int NT = T_ / FBc;                  // 32
    for (int it = 0; it < NT; it++) {
        __syncthreads();

        // ---- Stage regs (tile it+1) into other buffer; prefetch it+2 ----
        if (it + 1 < NT) {
            uint32_t* buf = smw + ((it + 1) & 1) * BUF_WORDS;
            uint32_t* Khi = buf;
            uint32_t* Vs  = buf + KHI_WORDS;
            #pragma unroll
            for (int i = 0; i < 4; i++) {
                const int r = r0 + 16 * i;
                const int dbase = c4 * 4;
                const float kf[4] = {ra[i].x, ra[i].y, ra[i].z, ra[i].w};
                #pragma unroll
                for (int u = 0; u < 4; u++) {
                    const int d = dbase + u;
                    Khi[r * FST_K + (d & ~7) + permc(d & 7)] = f2tf32(kf[u]);
                }
                uint4 vw;
                vw.x = f2tf32(rv[i].x); vw.y = f2tf32(rv[i].y);
                vw.z = f2tf32(rv[i].z); vw.w = f2tf32(rv[i].w);
                *(uint4*)&Vs[r * FST_V + dbase] = vw;
            }
            if (it + 2 < NT) {
                const size_t row = (size_t)(it + 2) * 64;
                #pragma unroll
                for (int i = 0; i < 4; i++) {
                    ra[i] = K4[(row + r0 + 16 * i) * 16];
                    rv[i] = V4[(row + r0 + 16 * i) * 16];
                }
            }
        }

        const uint32_t* buf = smw + (it & 1) * BUF_WORDS;
        const uint32_t* Khi = buf;
        const uint32_t* Vs  = buf + KHI_WORDS;

        // ---- S = Q @ K^T (single tf32) ----
        float sacc[8][4];
        #pragma unroll
        for (int j = 0; j < 8; j++)
            #pragma unroll
            for (int r = 0; r < 4; r++) sacc[j][r] = 0.f;

        #pragma unroll
        for (int s = 0; s < 8; s++) {
            #pragma unroll
            for (int jt = 0; jt < 8; jt++) {
                const uint2 kh2 = *(const uint2*)&Khi[(jt * 8 + g) * FST_K + s * 8 + 2 * tg];
                const uint32_t bhh[2] = {kh2.x, kh2.y};
                mma_tf32(sacc[jt], qh[s], bhh);
            }
        }

        // ---- Online softmax (rows g and g+8); e's stay in sacc regs ----
        float mx0 = -1e30f, mx1 = -1e30f;
        #pragma unroll
        for (int jt = 0; jt < 8; jt++) {
            mx0 = fmaxf(mx0, fmaxf(sacc[jt][0], sacc[jt][1]));
            mx1 = fmaxf(mx1, fmaxf(sacc[jt][2], sacc[jt][3]));
        }
        mx0 = fmaxf(mx0, __shfl_xor_sync(0xffffffffu, mx0, 1));
        mx0 = fmaxf(mx0, __shfl_xor_sync(0xffffffffu, mx0, 2));
        mx1 = fmaxf(mx1, __shfl_xor_sync(0xffffffffu, mx1, 1));
        mx1 = fmaxf(mx1, __shfl_xor_sync(0xffffffffu, mx1, 2));

        const float mn0 = fmaxf(m0, mx0), mn1 = fmaxf(m1, mx1);
        const float a0 = __expf(m0 - mn0), a1 = __expf(m1 - mn1);

        float rs0 = 0.f, rs1 = 0.f;
        #pragma unroll
        for (int jt = 0; jt < 8; jt++) {
            sacc[jt][0] = __expf(sacc[jt][0] - mn0);
            sacc[jt][1] = __expf(sacc[jt][1] - mn0);
            sacc[jt][2] = __expf(sacc[jt][2] - mn1);
            sacc[jt][3] = __expf(sacc[jt][3] - mn1);
            rs0 += sacc[jt][0] + sacc[jt][1];
            rs1 += sacc[jt][2] + sacc[jt][3];
        }
        rs0 += __shfl_xor_sync(0xffffffffu, rs0, 1);
        rs0 += __shfl_xor_sync(0xffffffffu, rs0, 2);
        rs1 += __shfl_xor_sync(0xffffffffu, rs1, 1);
        rs1 += __shfl_xor_sync(0xffffffffu, rs1, 2);

        l0 = l0 * a0 + rs0;
        l1 = l1 * a1 + rs1;
        m0 = mn0; m1 = mn1;
        #pragma unroll
        for (int jt = 0; jt < 8; jt++) {
            o[jt][0] *= a0; o[jt][1] *= a0;
            o[jt][2] *= a1; o[jt][3] *= a1;
        }

        // ---- O += P @ V : P direct from registers (permuted key slots).
        #pragma unroll
        for (int jt = 0; jt < 8; jt++) {
            const uint32_t pa[4] = {f2tf32(sacc[jt][0]), f2tf32(sacc[jt][2]),
                                    f2tf32(sacc[jt][1]), f2tf32(sacc[jt][3])};
            const uint32_t* v0row = &Vs[(jt * 8 + 2 * tg)     * FST_V + g];
            const uint32_t* v1row = &Vs[(jt * 8 + 2 * tg + 1) * FST_V + g];
            #pragma unroll
            for (int dt = 0; dt < 8; dt++) {
                const uint32_t vb[2] = {v0row[dt * 8], v1row[dt * 8]};
                mma_tf32(o[dt], pa, vb);
            }
        }
    }

    // ---- Epilogue: normalize, write to [B, T, H*HD] ----
    const float i0 = 1.0f / l0, i1 = 1.0f / l1;
    const int bb = bh >> 4, h = bh & 15;
    const int row0 = q0 + wr + g, row1 = row0 + 8;
    #pragma unroll
    for (int dt = 0; dt < 8; dt++) {
        const int dcol = h * HD_ + dt * 8 + 2 * tg;
        *(float2*)&g_o[((size_t)bb * T_ + row0) * D_ + dcol] =
            make_float2(o[dt][0] * i0, o[dt][1] * i0);
        *(float2*)&g_o[((size_t)bb * T_ + row1) * D_ + dcol] =
            make_float2(o[dt][2] * i1, o[dt][3] * i1);
    }
}

// ---------------------------------------------------------------------------
extern "C" void kernel_launch(void* const* d_in, const int* in_sizes, int n_in,
                              void* d_out, int out_size)
{
    const float* x  = (const float*)d_in[0];
    const float* Wq = (const float*)d_in[1];
    const float* bq = (const float*)d_in[2];
    const float* Wk = (const float*)d_in[3];
    const float* bk = (const float*)d_in[4];
    const float* Wv = (const float*)d_in[5];
    const float* bv = (const float*)d_in[6];
    const float* Wo = (const float*)d_in[7];
    const float* bo = (const float*)d_in[8];
    float* out = (float*)d_out;

    cudaFuncSetAttribute(gemm_tc, cudaFuncAttributeMaxDynamicSharedMemorySize,
                         GEMM_SMEM);
    cudaFuncSetAttribute(flash_tc, cudaFuncAttributeMaxDynamicSharedMemorySize,
                         FLASH_SMEM);

    dim3 gg(D_ / 128, MROWS / 128);          // (8, 64)
    gemm_tc<<<gg, 256, GEMM_SMEM>>>(x, Wq, bq, nullptr, 0);
    gemm_tc<<<gg, 256, GEMM_SMEM>>>(x, Wk, bk, nullptr, 1);
    gemm_tc<<<gg, 256, GEMM_SMEM>>>(x, Wv, bv, nullptr, 2);

    dim3 attn_grid(B_ * H_, T_ / FBr);       // (64, 16)
    flash_tc<<<attn_grid, 256, FLASH_SMEM>>>();

    gemm_tc<<<gg, 256, GEMM_SMEM>>>(nullptr, Wo, bo, out, 3);
}